// round 15
// baseline (speedup 1.0000x reference)
#include <cuda_runtime.h>
#include <cuda_fp16.h>
#include <math.h>
#include <stdint.h>

// ---------------- problem sizes ----------------
#define NN 4096
#define EE 49152
#define TT 262144
#define HH 256
#define EMB 64
#define AIN 92
#define EB 80
#define TB 40

// ---------------- device scratch (allocation-free) ----------------
__device__ float g_x   [(size_t)NN * HH];
__device__ float g_y   [(size_t)EE * HH];
__device__ float g_sums[(size_t)EE * HH];
__device__ float g_sumsh[(size_t)EE * HH];
__device__ float g_rbf [(size_t)TT * TB];
__device__ float g_val [(size_t)TT];

// fp16 gate/message buffers
__device__ __align__(256) __half g_hg0[(size_t)EE * HH];
__device__ __align__(256) __half g_hg1[(size_t)EE * HH];
__device__ __align__(256) __half g_hg3[(size_t)EE * HH];
__device__ __align__(256) __half g_hg4[(size_t)EE * HH];
__device__ __align__(256) __half g_hm [(size_t)TT * HH];

// fp16 state mirrors / fp16-only states + converted weights
__device__ __align__(256) __half g_hx [(size_t)NN * HH];
__device__ __align__(256) __half g_hy [(size_t)EE * HH];
__device__ __align__(256) __half g_hz [(size_t)TT * HH];   // z: fp16-only residual state
__device__ __align__(256) __half g_hh [(size_t)TT * EMB];
#define WT_EGGC(blk, w) (((size_t)(blk) * 5 + (w)) * 65536)
#define WT_ANG  ((size_t)60 * 65536)
#define WT_EDGE (WT_ANG + 16384)
__device__ __align__(256) __half g_wh [WT_EDGE + 16384];

// ---------------- helpers ----------------
__device__ __forceinline__ float fsig(float x)  { return __frcp_rn(1.f + __expf(-x)); }
__device__ __forceinline__ float fsilu(float x) { return x * fsig(x); }
__device__ __forceinline__ uint32_t h2u(__half2 h) { return *(uint32_t*)&h; }

__device__ __forceinline__ void unpack8(uint4 u, float f[8]) {
    __half2 h;
    h = *(__half2*)&u.x; f[0] = __low2float(h); f[1] = __high2float(h);
    h = *(__half2*)&u.y; f[2] = __low2float(h); f[3] = __high2float(h);
    h = *(__half2*)&u.z; f[4] = __low2float(h); f[5] = __high2float(h);
    h = *(__half2*)&u.w; f[6] = __low2float(h); f[7] = __high2float(h);
}
__device__ __forceinline__ uint4 pack8(const float f[8]) {
    uint4 u;
    u.x = h2u(__floats2half2_rn(f[0], f[1]));
    u.y = h2u(__floats2half2_rn(f[2], f[3]));
    u.z = h2u(__floats2half2_rn(f[4], f[5]));
    u.w = h2u(__floats2half2_rn(f[6], f[7]));
    return u;
}

__device__ __forceinline__ void red_add_v4(float* p, float4 v) {
    asm volatile("red.global.add.v4.f32 [%0], {%1,%2,%3,%4};"
                 :: "l"(p), "f"(v.x), "f"(v.y), "f"(v.z), "f"(v.w) : "memory");
}

#define CPA16(dst, src) asm volatile("cp.async.cg.shared.global [%0], [%1], 16;" :: "r"(dst), "l"(src))
#define CPA_COMMIT      asm volatile("cp.async.commit_group;")
#define CPA_WAIT0       asm volatile("cp.async.wait_group 0;")
#define CPA_WAIT1       asm volatile("cp.async.wait_group 1;")

__device__ __forceinline__ void mma_f16(float c[4], const uint32_t a[4], const uint32_t b[2]) {
    asm volatile(
        "mma.sync.aligned.m16n8k16.row.col.f32.f16.f16.f32 "
        "{%0,%1,%2,%3}, {%4,%5,%6,%7}, {%8,%9}, {%0,%1,%2,%3};"
        : "+f"(c[0]), "+f"(c[1]), "+f"(c[2]), "+f"(c[3])
        : "r"(a[0]), "r"(a[1]), "r"(a[2]), "r"(a[3]), "r"(b[0]), "r"(b[1]));
}

// ================= FP16 GEMM, BN = 256 (256 thr, 8 warps, warp tile 64x64) =================
// MODE 0: H[sel] = fp16(acc+bias); optional epilogue zeroing of Z0 (y==0) / Z1 (y==1).
// MODE 1: Cf = silu(LN(acc+bias)) fp32 + fp16 mirror Ch.
// MODE 2: Ch = silu(LN(acc+bias)) fp16 only.
#define ASZH 3072
#define BSZH 6144
#define F16SMEM ((3 * ASZH + 3 * BSZH) * 2)

template <int MODE>
__global__ __launch_bounds__(256, 1)
void f16_gemm256_kernel(const __half* __restrict__ A,
                        const __half* B0, const __half* B1, const __half* B2, const __half* B3,
                        const float* bi0, const float* bi1, const float* bi2, const float* bi3,
                        __half* H0, __half* H1, __half* H2, __half* H3,
                        float* __restrict__ Cf, __half* __restrict__ Ch,
                        const float* __restrict__ lns, const float* __restrict__ lnb,
                        float* __restrict__ Z0, float* __restrict__ Z1,
                        int M, int K) {
    const __half* B; const float* bias; __half* H;
    switch (blockIdx.y) {
        case 0:  B = B0; bias = bi0; H = H0; break;
        case 1:  B = B1; bias = bi1; H = H1; break;
        case 2:  B = B2; bias = bi2; H = H2; break;
        default: B = B3; bias = bi3; H = H3; break;
    }

    extern __shared__ __half hsm[];
    const uint32_t smem_u = (uint32_t)__cvta_generic_to_shared(hsm);

    const int tid = threadIdx.x;
    const int lane = tid & 31;
    const int warp = tid >> 5;
    const int wm = warp & 1;
    const int wn = warp >> 1;
    const int row0 = blockIdx.x * 128;
    const int mbase = wm * 64;
    const int nbase = wn * 64;
    const int g = lane >> 2;
    const int tg = lane & 3;

    const int ar = tid >> 1, ca = tid & 1;
    const int br0 = tid >> 1, cb0 = tid & 1;
    const int br1 = (tid + 256) >> 1, cb1 = tid & 1;

#define LOADSTAGE(st, k0) do {                                                           \
        CPA16(smem_u + (uint32_t)(((st) * ASZH + ar * 24 + ca * 8) * 2),                 \
              A + (size_t)(row0 + ar) * K + (k0) + ca * 8);                              \
        CPA16(smem_u + (uint32_t)((3 * ASZH + (st) * BSZH + br0 * 24 + cb0 * 8) * 2),    \
              B + (size_t)br0 * K + (k0) + cb0 * 8);                                     \
        CPA16(smem_u + (uint32_t)((3 * ASZH + (st) * BSZH + br1 * 24 + cb1 * 8) * 2),    \
              B + (size_t)br1 * K + (k0) + cb1 * 8);                                     \
        CPA_COMMIT;                                                                      \
    } while (0)

    float acc[4][8][4];
    #pragma unroll
    for (int i = 0; i < 4; i++)
        #pragma unroll
        for (int j = 0; j < 8; j++)
            #pragma unroll
            for (int t = 0; t < 4; t++) acc[i][j][t] = 0.f;

    LOADSTAGE(0, 0);
    LOADSTAGE(1, 16);

    int st = 0;
    for (int k0 = 0; k0 < K; k0 += 16) {
        if (k0 + 16 >= K) { CPA_WAIT0; } else { CPA_WAIT1; }
        __syncthreads();
        if (k0 + 32 < K) {
            int nst = st + 2; if (nst >= 3) nst -= 3;
            LOADSTAGE(nst, k0 + 32);
        }
        const __half* aB = hsm + st * ASZH;
        const __half* bB = hsm + 3 * ASZH + st * BSZH;
        uint32_t afr[4][4];
        #pragma unroll
        for (int i = 0; i < 4; i++) {
            int r = mbase + i * 16 + g;
            afr[i][0] = *(const uint32_t*)&aB[r * 24 + 2 * tg];
            afr[i][1] = *(const uint32_t*)&aB[(r + 8) * 24 + 2 * tg];
            afr[i][2] = *(const uint32_t*)&aB[r * 24 + 2 * tg + 8];
            afr[i][3] = *(const uint32_t*)&aB[(r + 8) * 24 + 2 * tg + 8];
        }
        uint32_t bfr[8][2];
        #pragma unroll
        for (int j = 0; j < 8; j++) {
            int n = nbase + j * 8 + g;
            bfr[j][0] = *(const uint32_t*)&bB[n * 24 + 2 * tg];
            bfr[j][1] = *(const uint32_t*)&bB[n * 24 + 2 * tg + 8];
        }
        #pragma unroll
        for (int i = 0; i < 4; i++)
            #pragma unroll
            for (int j = 0; j < 8; j++)
                mma_f16(acc[i][j], afr[i], bfr[j]);
        st++; if (st >= 3) st = 0;
    }
#undef LOADSTAGE

    // bias add
    #pragma unroll
    for (int j = 0; j < 8; j++) {
        int c = nbase + j * 8 + 2 * tg;
        float2 bb = *(const float2*)&bias[c];
        #pragma unroll
        for (int i = 0; i < 4; i++) {
            acc[i][j][0] += bb.x; acc[i][j][1] += bb.y;
            acc[i][j][2] += bb.x; acc[i][j][3] += bb.y;
        }
    }

    if (MODE == 0) {
        #pragma unroll
        for (int j = 0; j < 8; j++) {
            int c = nbase + j * 8 + 2 * tg;
            #pragma unroll
            for (int i = 0; i < 4; i++) {
                int r = row0 + mbase + i * 16 + g;
                *(uint32_t*)&H[(size_t)r * 256 + c] = h2u(__floats2half2_rn(acc[i][j][0], acc[i][j][1]));
                *(uint32_t*)&H[(size_t)(r + 8) * 256 + c] = h2u(__floats2half2_rn(acc[i][j][2], acc[i][j][3]));
            }
        }
        float* Z = (blockIdx.y == 0) ? Z0 : ((blockIdx.y == 1) ? Z1 : nullptr);
        if (Z) {
            float4* zrow = (float4*)(Z + (size_t)row0 * 256);
            float4 zv = make_float4(0.f, 0.f, 0.f, 0.f);
            #pragma unroll
            for (int i = 0; i < 32; i++) zrow[tid + i * 256] = zv;
        }
    } else {
        // fused LayerNorm + SiLU
        __syncthreads();
        float* part = (float*)hsm;
        float s1[8], s2[8];
        #pragma unroll
        for (int k = 0; k < 8; k++) { s1[k] = 0.f; s2[k] = 0.f; }
        #pragma unroll
        for (int i = 0; i < 4; i++)
            #pragma unroll
            for (int j = 0; j < 8; j++) {
                float a0 = acc[i][j][0], a1 = acc[i][j][1];
                float a2 = acc[i][j][2], a3 = acc[i][j][3];
                s1[2 * i] += a0 + a1;       s2[2 * i] += a0 * a0 + a1 * a1;
                s1[2 * i + 1] += a2 + a3;   s2[2 * i + 1] += a2 * a2 + a3 * a3;
            }
        #pragma unroll
        for (int off = 1; off <= 2; off <<= 1)
            #pragma unroll
            for (int k = 0; k < 8; k++) {
                s1[k] += __shfl_xor_sync(0xffffffffu, s1[k], off);
                s2[k] += __shfl_xor_sync(0xffffffffu, s2[k], off);
            }
        if (tg == 0) {
            #pragma unroll
            for (int i = 0; i < 4; i++) {
                int r = mbase + i * 16 + g;
                part[(wn * 128 + r) * 2 + 0] = s1[2 * i];
                part[(wn * 128 + r) * 2 + 1] = s2[2 * i];
                part[(wn * 128 + r + 8) * 2 + 0] = s1[2 * i + 1];
                part[(wn * 128 + r + 8) * 2 + 1] = s2[2 * i + 1];
            }
        }
        __syncthreads();
        float mu[8], inv[8];
        #pragma unroll
        for (int i = 0; i < 4; i++)
            #pragma unroll
            for (int h = 0; h < 2; h++) {
                int r = mbase + i * 16 + g + h * 8;
                float S1 = 0.f, S2 = 0.f;
                #pragma unroll
                for (int w = 0; w < 4; w++) {
                    S1 += part[(w * 128 + r) * 2 + 0];
                    S2 += part[(w * 128 + r) * 2 + 1];
                }
                float m = S1 * (1.f / 256.f);
                float v = S2 * (1.f / 256.f) - m * m;
                mu[2 * i + h] = m;
                inv[2 * i + h] = rsqrtf(v + 1e-5f);
            }
        #pragma unroll
        for (int j = 0; j < 8; j++) {
            int c = nbase + j * 8 + 2 * tg;
            float2 sc = *(const float2*)&lns[c];
            float2 sb = *(const float2*)&lnb[c];
            #pragma unroll
            for (int i = 0; i < 4; i++) {
                #pragma unroll
                for (int h = 0; h < 2; h++) {
                    int r = row0 + mbase + i * 16 + g + h * 8;
                    float o0 = fsilu((acc[i][j][2 * h] - mu[2 * i + h]) * inv[2 * i + h] * sc.x + sb.x);
                    float o1 = fsilu((acc[i][j][2 * h + 1] - mu[2 * i + h]) * inv[2 * i + h] * sc.y + sb.y);
                    if (MODE == 1)
                        *(float2*)&Cf[(size_t)r * 256 + c] = make_float2(o0, o1);
                    *(uint32_t*)&Ch[(size_t)r * 256 + c] = h2u(__floats2half2_rn(o0, o1));
                }
            }
        }
    }
}

// ---------------- weight convert + transpose ----------------
__global__ void wconv_kernel(const float* __restrict__ in, __half* __restrict__ out,
                             int K, int N) {
    __shared__ float t[32][33];
    const float* src = in + (size_t)blockIdx.z * K * N;
    __half* dst = out + (size_t)blockIdx.z * K * N;
    int k0 = blockIdx.x * 32, n0 = blockIdx.y * 32;
    int tx = threadIdx.x, ty = threadIdx.y;
    #pragma unroll
    for (int i = 0; i < 4; i++)
        t[ty + 8 * i][tx] = src[(size_t)(k0 + ty + 8 * i) * N + n0 + tx];
    __syncthreads();
    #pragma unroll
    for (int i = 0; i < 4; i++)
        dst[(size_t)(n0 + ty + 8 * i) * K + k0 + tx] = __float2half(t[tx][ty + 8 * i]);
}

// ---------------- fp32 SGEMM (odd shapes); mode1: fused LN+SiLU, fp16-only out ----------------
__global__ void sgemm_bias_kernel(const float* __restrict__ A, const float* __restrict__ B,
                                  const float* __restrict__ bias, float* __restrict__ C,
                                  __half* __restrict__ Ch,
                                  int M, int N, int K,
                                  const float* __restrict__ lns, const float* __restrict__ lnb,
                                  int mode) {
    __shared__ float As[16][64];
    __shared__ float Bs[16][64];
    const int tid = threadIdx.x;
    const int tcol = tid & 15;
    const int trow = tid >> 4;
    const int row0 = blockIdx.y * 64;
    const int col0 = blockIdx.x * 64;

    float acc[4][4] = {};
    for (int k0 = 0; k0 < K; k0 += 16) {
        #pragma unroll
        for (int i = 0; i < 4; i++) {
            int idx = tid + i * 256;
            int m = idx >> 4, kk = idx & 15;
            int gk = k0 + kk;
            As[kk][m] = (gk < K) ? A[(size_t)(row0 + m) * K + gk] : 0.f;
        }
        #pragma unroll
        for (int i = 0; i < 4; i++) {
            int idx = tid + i * 256;
            int kk = idx >> 6, n = idx & 63;
            int gk = k0 + kk;
            Bs[kk][n] = (gk < K) ? B[(size_t)gk * N + (col0 + n)] : 0.f;
        }
        __syncthreads();
        #pragma unroll
        for (int kk = 0; kk < 16; kk++) {
            float a[4], b[4];
            #pragma unroll
            for (int i = 0; i < 4; i++) a[i] = As[kk][trow * 4 + i];
            #pragma unroll
            for (int j = 0; j < 4; j++) b[j] = Bs[kk][tcol * 4 + j];
            #pragma unroll
            for (int i = 0; i < 4; i++)
                #pragma unroll
                for (int j = 0; j < 4; j++) acc[i][j] += a[i] * b[j];
        }
        __syncthreads();
    }
    #pragma unroll
    for (int j = 0; j < 4; j++) {
        float bv = bias[col0 + tcol * 4 + j];
        #pragma unroll
        for (int i = 0; i < 4; i++) acc[i][j] += bv;
    }
    if (mode == 0) {
        #pragma unroll
        for (int i = 0; i < 4; i++) {
            int r = row0 + trow * 4 + i;
            #pragma unroll
            for (int j = 0; j < 4; j++)
                C[(size_t)r * N + col0 + tcol * 4 + j] = acc[i][j];
        }
    } else {
        #pragma unroll
        for (int i = 0; i < 4; i++) {
            float rs = acc[i][0] + acc[i][1] + acc[i][2] + acc[i][3];
            float rq = acc[i][0] * acc[i][0] + acc[i][1] * acc[i][1] +
                       acc[i][2] * acc[i][2] + acc[i][3] * acc[i][3];
            #pragma unroll
            for (int o = 1; o <= 8; o <<= 1) {
                rs += __shfl_xor_sync(0xffffffffu, rs, o);
                rq += __shfl_xor_sync(0xffffffffu, rq, o);
            }
            float mval = rs * (1.f / 64.f);
            float vval = rq * (1.f / 64.f) - mval * mval;
            float inv = rsqrtf(vval + 1e-5f);
            int r = row0 + trow * 4 + i;
            int c = tcol * 4;
            float o0 = fsilu((acc[i][0] - mval) * inv * lns[c + 0] + lnb[c + 0]);
            float o1 = fsilu((acc[i][1] - mval) * inv * lns[c + 1] + lnb[c + 1]);
            float o2 = fsilu((acc[i][2] - mval) * inv * lns[c + 2] + lnb[c + 2]);
            float o3 = fsilu((acc[i][3] - mval) * inv * lns[c + 3] + lnb[c + 3]);
            uint2 u;
            u.x = h2u(__floats2half2_rn(o0, o1));
            u.y = h2u(__floats2half2_rn(o2, o3));
            *(uint2*)&Ch[(size_t)r * 64 + c] = u;
        }
    }
}

// ---------------- LayerNorm + SiLU (warp per row) + fp16 mirror ----------------
__global__ void ln_silu_kernel(const float* __restrict__ in, const float* __restrict__ s,
                               const float* __restrict__ b, float* __restrict__ out,
                               __half* __restrict__ outh, int M, int Hd) {
    int row = blockIdx.x * (blockDim.x >> 5) + (threadIdx.x >> 5);
    if (row >= M) return;
    int lane = threadIdx.x & 31;
    int per = Hd >> 5;
    float v[8];
    const float* rin = in + (size_t)row * Hd;
    float sum = 0.f;
    for (int i = 0; i < per; i++) { v[i] = rin[lane + i * 32]; sum += v[i]; }
    #pragma unroll
    for (int o = 16; o; o >>= 1) sum += __shfl_xor_sync(0xffffffffu, sum, o);
    float mu = sum / Hd;
    float vs = 0.f;
    for (int i = 0; i < per; i++) { float d = v[i] - mu; vs += d * d; }
    #pragma unroll
    for (int o = 16; o; o >>= 1) vs += __shfl_xor_sync(0xffffffffu, vs, o);
    float inv = rsqrtf(vs / Hd + 1e-5f);
    float* rout = out + (size_t)row * Hd;
    __half* hout = outh + (size_t)row * Hd;
    for (int i = 0; i < per; i++) {
        int c = lane + i * 32;
        float t = (v[i] - mu) * inv * s[c] + b[c];
        float sl = fsilu(t);
        rout[c] = sl;
        hout[c] = __float2half(sl);
    }
}

// ---------------- EGGC node update ----------------
__global__ void node_update_kernel(const __half* __restrict__ g3, const float* __restrict__ sumsh,
                                   const float* __restrict__ sums, const float* __restrict__ s,
                                   const float* __restrict__ b, float* __restrict__ x,
                                   __half* __restrict__ xh, int M) {
    int row = blockIdx.x * 8 + (threadIdx.x >> 5);
    if (row >= M) return;
    int lane = threadIdx.x & 31;
    size_t base = (size_t)row * HH;
    float v[8];
    float sum = 0.f;
    #pragma unroll
    for (int i = 0; i < 8; i++) {
        int c = lane + i * 32;
        float val = __half2float(g3[base + c]) + sumsh[base + c] / (sums[base + c] + 1e-6f);
        v[i] = val; sum += val;
    }
    #pragma unroll
    for (int o = 16; o; o >>= 1) sum += __shfl_xor_sync(0xffffffffu, sum, o);
    float mu = sum / HH;
    float vs = 0.f;
    #pragma unroll
    for (int i = 0; i < 8; i++) { float d = v[i] - mu; vs += d * d; }
    #pragma unroll
    for (int o = 16; o; o >>= 1) vs += __shfl_xor_sync(0xffffffffu, vs, o);
    float inv = rsqrtf(vs / HH + 1e-5f);
    #pragma unroll
    for (int i = 0; i < 8; i++) {
        int c = lane + i * 32;
        float t = (v[i] - mu) * inv * s[c] + b[c];
        float nv = x[base + c] + fsilu(t);
        x[base + c] = nv;
        xh[base + c] = __float2half(nv);
    }
}

// ---------------- fused EGGC message + segment sums + edge LN/SiLU residual ----------------
// EDGE16=0: edge residual in fp32 edgef + fp16 mirror.  EDGE16=1: fp16-only edgefh.
template <int EDGE16>
__global__ void eggc_msg_ln_kernel(const uint4* __restrict__ g0, const uint4* __restrict__ g1,
                                   const uint4* __restrict__ g4, const uint4* __restrict__ m,
                                   const int* __restrict__ src, const int* __restrict__ dst,
                                   float* __restrict__ sum_s, float* __restrict__ sum_sh,
                                   const float4* __restrict__ lns, const float4* __restrict__ lnb,
                                   float4* __restrict__ edgef, __half* __restrict__ edgefh, int Ecnt) {
    int e = blockIdx.x * 8 + (threadIdx.x >> 5);
    if (e >= Ecnt) return;
    int lane = threadIdx.x & 31;
    int s = src[e], d = dst[e];

    float m8[8], a8[8], b8[8], u8[8];
    unpack8(m[(size_t)e * 32 + lane], m8);
    unpack8(g0[(size_t)s * 32 + lane], a8);
    unpack8(g1[(size_t)d * 32 + lane], b8);
    unpack8(g4[(size_t)s * 32 + lane], u8);

    float mv[8], sg[8];
    #pragma unroll
    for (int k = 0; k < 8; k++) {
        mv[k] = m8[k] + a8[k] + b8[k];
        sg[k] = fsig(mv[k]);
    }

    float* ps  = sum_s  + (size_t)d * HH + lane * 8;
    float* psh = sum_sh + (size_t)d * HH + lane * 8;
    red_add_v4(ps,     make_float4(sg[0], sg[1], sg[2], sg[3]));
    red_add_v4(ps + 4, make_float4(sg[4], sg[5], sg[6], sg[7]));
    red_add_v4(psh,     make_float4(u8[0] * sg[0], u8[1] * sg[1], u8[2] * sg[2], u8[3] * sg[3]));
    red_add_v4(psh + 4, make_float4(u8[4] * sg[4], u8[5] * sg[5], u8[6] * sg[6], u8[7] * sg[7]));

    float sum = 0.f;
    #pragma unroll
    for (int k = 0; k < 8; k++) sum += mv[k];
    #pragma unroll
    for (int o = 16; o; o >>= 1) sum += __shfl_xor_sync(0xffffffffu, sum, o);
    float mu = sum * (1.f / 256.f);
    float vs = 0.f;
    #pragma unroll
    for (int k = 0; k < 8; k++) { float dd = mv[k] - mu; vs += dd * dd; }
    #pragma unroll
    for (int o = 16; o; o >>= 1) vs += __shfl_xor_sync(0xffffffffu, vs, o);
    float inv = rsqrtf(vs * (1.f / 256.f) + 1e-5f);

    float4 sc0 = lns[lane * 2], sc1 = lns[lane * 2 + 1];
    float4 bb0 = lnb[lane * 2], bb1 = lnb[lane * 2 + 1];
    float upd[8];
    {
        float scf[8] = {sc0.x, sc0.y, sc0.z, sc0.w, sc1.x, sc1.y, sc1.z, sc1.w};
        float sbf[8] = {bb0.x, bb0.y, bb0.z, bb0.w, bb1.x, bb1.y, bb1.z, bb1.w};
        #pragma unroll
        for (int k = 0; k < 8; k++)
            upd[k] = fsilu((mv[k] - mu) * inv * scf[k] + sbf[k]);
    }

    if (EDGE16) {
        uint4* eh = (uint4*)&edgefh[(size_t)e * 256 + lane * 8];
        float ef[8];
        unpack8(*eh, ef);
        #pragma unroll
        for (int k = 0; k < 8; k++) ef[k] += upd[k];
        *eh = pack8(ef);
    } else {
        size_t mb = (size_t)e * 64 + lane * 2;
        float4 ef0 = edgef[mb], ef1 = edgef[mb + 1];
        ef0.x += upd[0]; ef0.y += upd[1]; ef0.z += upd[2]; ef0.w += upd[3];
        ef1.x += upd[4]; ef1.y += upd[5]; ef1.z += upd[6]; ef1.w += upd[7];
        edgef[mb] = ef0;
        edgef[mb + 1] = ef1;
        float ef[8] = {ef0.x, ef0.y, ef0.z, ef0.w, ef1.x, ef1.y, ef1.z, ef1.w};
        *(uint4*)&edgefh[(size_t)e * 256 + lane * 8] = pack8(ef);
    }
}

// ---------------- geometry + RBF (coalesced elementwise forms) ----------------
__global__ void cos_kernel(const float* __restrict__ r, const int* __restrict__ lsrc,
                           const int* __restrict__ ldst, float* __restrict__ out, int Tcnt) {
    int t = blockIdx.x * blockDim.x + threadIdx.x;
    if (t >= Tcnt) return;
    int a = lsrc[t], b = ldst[t];
    float ax = r[(size_t)a * 3 + 0], ay = r[(size_t)a * 3 + 1], az = r[(size_t)a * 3 + 2];
    float bx = r[(size_t)b * 3 + 0], by = r[(size_t)b * 3 + 1], bz = r[(size_t)b * 3 + 2];
    float dot = -(ax * bx + ay * by + az * bz);
    float na = sqrtf(ax * ax + ay * ay + az * az);
    float nb = sqrtf(bx * bx + by * by + bz * bz);
    float c = dot / (na * nb);
    out[t] = fminf(1.f, fmaxf(-1.f, c));
}

__global__ void bondlen_kernel(const float* __restrict__ r, float* __restrict__ out, int Ecnt) {
    int e = blockIdx.x * blockDim.x + threadIdx.x;
    if (e >= Ecnt) return;
    float x = r[(size_t)e * 3 + 0], y = r[(size_t)e * 3 + 1], z = r[(size_t)e * 3 + 2];
    out[e] = sqrtf(x * x + y * y + z * z);
}

__global__ void rbf_kernel(const float* __restrict__ vals, float* __restrict__ out,
                           long long M, int bins, float vmin, float vmax) {
    long long idx = (long long)blockIdx.x * blockDim.x + threadIdx.x;
    long long total = M * bins;
    if (idx >= total) return;
    long long t = idx / bins;
    int k = (int)(idx % bins);
    float spacing = (vmax - vmin) / (bins - 1);
    float center = vmin + k * spacing;
    float gamma = 1.f / spacing;
    float d = vals[t] - center;
    out[idx] = __expf(-gamma * d * d);
}

// ---------------- output head ----------------
__global__ void fc_kernel(const float* __restrict__ x, const float* __restrict__ W,
                          const float* __restrict__ b, float* __restrict__ out) {
    int atom = blockIdx.x * 8 + (threadIdx.x >> 5);
    if (atom >= NN) return;
    int lane = threadIdx.x & 31;
    float sum = 0.f;
    #pragma unroll
    for (int i = 0; i < 8; i++) {
        int c = lane + i * 32;
        sum += x[(size_t)atom * HH + c] * W[c];
    }
    #pragma unroll
    for (int o = 16; o; o >>= 1) sum += __shfl_xor_sync(0xffffffffu, sum, o);
    if (lane == 0) out[1 + atom] = sum + b[0];
}

__global__ void mean_kernel(float* out) {
    __shared__ float sh[32];
    float s = 0.f;
    for (int i = threadIdx.x; i < NN; i += 1024) s += out[1 + i];
    #pragma unroll
    for (int o = 16; o; o >>= 1) s += __shfl_xor_sync(0xffffffffu, s, o);
    if ((threadIdx.x & 31) == 0) sh[threadIdx.x >> 5] = s;
    __syncthreads();
    if (threadIdx.x < 32) {
        s = sh[threadIdx.x];
        #pragma unroll
        for (int o = 16; o; o >>= 1) s += __shfl_xor_sync(0xffffffffu, s, o);
        if (threadIdx.x == 0) out[0] = s / (float)NN;
    }
}

extern "C" void kernel_launch(void* const* d_in, const int* in_sizes, int n_in,
                              void* d_out, int out_size) {
    const float* atom_features = (const float*)d_in[0];
    const float* r    = (const float*)d_in[1];
    const int*   src  = (const int*)d_in[2];
    const int*   dst  = (const int*)d_in[3];
    const int*   lsrc = (const int*)d_in[4];
    const int*   ldst = (const int*)d_in[5];
    const float* atom_W    = (const float*)d_in[6];
    const float* atom_b    = (const float*)d_in[7];
    const float* atom_ln_s = (const float*)d_in[8];
    const float* atom_ln_b = (const float*)d_in[9];
    const float* edge_W1    = (const float*)d_in[10];
    const float* edge_b1    = (const float*)d_in[11];
    const float* edge_ln1_s = (const float*)d_in[12];
    const float* edge_ln1_b = (const float*)d_in[13];
    const float* edge_W2    = (const float*)d_in[14];
    const float* edge_b2    = (const float*)d_in[15];
    const float* edge_ln2_s = (const float*)d_in[16];
    const float* edge_ln2_b = (const float*)d_in[17];
    const float* ang_W1    = (const float*)d_in[18];
    const float* ang_b1    = (const float*)d_in[19];
    const float* ang_ln1_s = (const float*)d_in[20];
    const float* ang_ln1_b = (const float*)d_in[21];
    const float* ang_W2    = (const float*)d_in[22];
    const float* ang_b2    = (const float*)d_in[23];
    const float* ang_ln2_s = (const float*)d_in[24];
    const float* ang_ln2_b = (const float*)d_in[25];
    const float* eggc_W    = (const float*)d_in[26];
    const float* eggc_b    = (const float*)d_in[27];
    const float* eggc_ln_s = (const float*)d_in[28];
    const float* eggc_ln_b = (const float*)d_in[29];
    const float* fc_W = (const float*)d_in[30];
    const float* fc_b = (const float*)d_in[31];
    float* out = (float*)d_out;

    float *px, *py, *psums, *psumsh, *prbf, *pval;
    __half *hg0, *hg1, *hg3, *hg4, *hm;
    __half *hx, *hy, *hz, *hh, *wh;
    cudaGetSymbolAddress((void**)&px,    g_x);
    cudaGetSymbolAddress((void**)&py,    g_y);
    cudaGetSymbolAddress((void**)&psums, g_sums);
    cudaGetSymbolAddress((void**)&psumsh,g_sumsh);
    cudaGetSymbolAddress((void**)&prbf,  g_rbf);
    cudaGetSymbolAddress((void**)&pval,  g_val);
    cudaGetSymbolAddress((void**)&hg0,   g_hg0);
    cudaGetSymbolAddress((void**)&hg1,   g_hg1);
    cudaGetSymbolAddress((void**)&hg3,   g_hg3);
    cudaGetSymbolAddress((void**)&hg4,   g_hg4);
    cudaGetSymbolAddress((void**)&hm,    g_hm);
    cudaGetSymbolAddress((void**)&hx,    g_hx);
    cudaGetSymbolAddress((void**)&hy,    g_hy);
    cudaGetSymbolAddress((void**)&hz,    g_hz);
    cudaGetSymbolAddress((void**)&hh,    g_hh);
    cudaGetSymbolAddress((void**)&wh,    g_wh);

    cudaFuncSetAttribute(f16_gemm256_kernel<0>, cudaFuncAttributeMaxDynamicSharedMemorySize, F16SMEM);
    cudaFuncSetAttribute(f16_gemm256_kernel<1>, cudaFuncAttributeMaxDynamicSharedMemorySize, F16SMEM);
    cudaFuncSetAttribute(f16_gemm256_kernel<2>, cudaFuncAttributeMaxDynamicSharedMemorySize, F16SMEM);

    // ---- convert + transpose weights to fp16 [N,K] ----
    {
        dim3 tb(32, 8);
        wconv_kernel<<<dim3(8, 8, 60), tb>>>(eggc_W, wh, 256, 256);
        wconv_kernel<<<dim3(2, 8, 1), tb>>>(ang_W2, wh + WT_ANG, 64, 256);
        wconv_kernel<<<dim3(2, 8, 1), tb>>>(edge_W2, wh + WT_EDGE, 64, 256);
    }

    // ---- angle branch: z = fp16-only state ----
    cos_kernel<<<TT / 256, 256>>>(r, lsrc, ldst, pval, TT);
    {
        long long total = (long long)TT * TB;
        rbf_kernel<<<(unsigned)((total + 255) / 256), 256>>>(pval, prbf, TT, TB, -1.f, 1.f);
    }
    {
        dim3 grid(1, TT / 64);
        sgemm_bias_kernel<<<grid, 256>>>(prbf, ang_W1, ang_b1, nullptr, hh,
                                         TT, EMB, TB, ang_ln1_s, ang_ln1_b, 1);
    }
    {
        dim3 grid(TT / 128, 1);
        f16_gemm256_kernel<2><<<grid, 256, F16SMEM>>>(
            hh, wh + WT_ANG, wh + WT_ANG, wh + WT_ANG, wh + WT_ANG,
            ang_b2, ang_b2, ang_b2, ang_b2,
            nullptr, nullptr, nullptr, nullptr,
            nullptr, hz, ang_ln2_s, ang_ln2_b, nullptr, nullptr, TT, EMB);
    }

    // ---- edge branch: y fp32 + fp16 mirror ----
    bondlen_kernel<<<EE / 256, 256>>>(r, pval, EE);
    {
        long long total = (long long)EE * EB;
        rbf_kernel<<<(unsigned)((total + 255) / 256), 256>>>(pval, prbf, EE, EB, 0.f, 8.f);
    }
    {
        dim3 grid(1, EE / 64);
        sgemm_bias_kernel<<<grid, 256>>>(prbf, edge_W1, edge_b1, nullptr, hh,
                                         EE, EMB, EB, edge_ln1_s, edge_ln1_b, 1);
    }
    {
        dim3 grid(EE / 128, 1);
        f16_gemm256_kernel<1><<<grid, 256, F16SMEM>>>(
            hh, wh + WT_EDGE, wh + WT_EDGE, wh + WT_EDGE, wh + WT_EDGE,
            edge_b2, edge_b2, edge_b2, edge_b2,
            nullptr, nullptr, nullptr, nullptr,
            py, hy, edge_ln2_s, edge_ln2_b, nullptr, nullptr, EE, EMB);
    }

    // ---- atom branch ----
    {
        dim3 grid(HH / 64, NN / 64);
        sgemm_bias_kernel<<<grid, 256>>>(atom_features, atom_W, atom_b, px, nullptr,
                                         NN, HH, AIN, nullptr, nullptr, 0);
    }
    ln_silu_kernel<<<NN / 8, 256>>>(px, atom_ln_s, atom_ln_b, px, hx, NN, HH);

    // ---- 12 EGGC blocks ----
    for (int blk = 0; blk < 12; blk++) {
        bool line = (blk < 8) && (blk & 1);
        float* nodef = line ? py : px;
        __half* nodeh = line ? hy : hx;
        int n        = line ? EE : NN;
        __half* edgeh = line ? hz : hy;
        int e        = line ? TT : EE;
        const int* gs = line ? lsrc : src;
        const int* gd = line ? ldst : dst;
        const float* bb = eggc_b   + (size_t)blk * 5 * HH;
        const float* ls = eggc_ln_s + (size_t)blk * 2 * HH;
        const float* lb = eggc_ln_b + (size_t)blk * 2 * HH;

        // 4 node-side GEMMs in one launch (shared A); also zeros psums (y=0) and psumsh (y=1)
        {
            dim3 grid(n / 128, 4);
            f16_gemm256_kernel<0><<<grid, 256, F16SMEM>>>(
                nodeh,
                wh + WT_EGGC(blk, 0), wh + WT_EGGC(blk, 1), wh + WT_EGGC(blk, 3), wh + WT_EGGC(blk, 4),
                bb + 0 * HH, bb + 1 * HH, bb + 3 * HH, bb + 4 * HH,
                hg0, hg1, hg3, hg4,
                nullptr, nullptr, nullptr, nullptr,
                psums, psumsh, n, HH);
        }
        // edge gate GEMM -> hm (fp16)
        {
            dim3 grid(e / 128, 1);
            f16_gemm256_kernel<0><<<grid, 256, F16SMEM>>>(
                edgeh,
                wh + WT_EGGC(blk, 2), wh + WT_EGGC(blk, 2), wh + WT_EGGC(blk, 2), wh + WT_EGGC(blk, 2),
                bb + 2 * HH, bb + 2 * HH, bb + 2 * HH, bb + 2 * HH,
                hm, hm, hm, hm,
                nullptr, nullptr, nullptr, nullptr,
                nullptr, nullptr, e, HH);
        }

        if (line) {
            eggc_msg_ln_kernel<1><<<e / 8, 256>>>((const uint4*)hg0, (const uint4*)hg1,
                                                  (const uint4*)hg4, (const uint4*)hm,
                                                  gs, gd, psums, psumsh,
                                                  (const float4*)(ls + HH), (const float4*)(lb + HH),
                                                  nullptr, hz, e);
        } else {
            eggc_msg_ln_kernel<0><<<e / 8, 256>>>((const uint4*)hg0, (const uint4*)hg1,
                                                  (const uint4*)hg4, (const uint4*)hm,
                                                  gs, gd, psums, psumsh,
                                                  (const float4*)(ls + HH), (const float4*)(lb + HH),
                                                  (float4*)py, hy, e);
        }

        node_update_kernel<<<(n + 7) / 8, 256>>>(hg3, psumsh, psums, ls, lb, nodef, nodeh, n);
    }

    // ---- output head ----
    fc_kernel<<<(NN + 7) / 8, 256>>>(px, fc_W, fc_b, out);
    mean_kernel<<<1, 1024>>>(out);
}

// round 16
// speedup vs baseline: 1.4266x; 1.4266x over previous
#include <cuda_runtime.h>
#include <cuda_fp16.h>
#include <math.h>
#include <stdint.h>

// ---------------- problem sizes ----------------
#define NN 4096
#define EE 49152
#define TT 262144
#define HH 256
#define EMB 64
#define AIN 92
#define EB 80
#define TB 40

// ---------------- device scratch (allocation-free) ----------------
__device__ float g_x   [(size_t)NN * HH];
__device__ float g_y   [(size_t)EE * HH];
__device__ float g_sums[(size_t)EE * HH];
__device__ float g_sumsh[(size_t)EE * HH];
__device__ float g_rbf [(size_t)TT * TB];
__device__ float g_val [(size_t)TT];

// fp16 gate/message buffers
__device__ __align__(256) __half g_hg0[(size_t)EE * HH];
__device__ __align__(256) __half g_hg1[(size_t)EE * HH];
__device__ __align__(256) __half g_hg3[(size_t)EE * HH];
__device__ __align__(256) __half g_hg4[(size_t)EE * HH];
__device__ __align__(256) __half g_hm [(size_t)TT * HH];

// fp16 state mirrors / fp16-only states + converted weights
__device__ __align__(256) __half g_hx [(size_t)NN * HH];
__device__ __align__(256) __half g_hy [(size_t)EE * HH];
__device__ __align__(256) __half g_hz [(size_t)TT * HH];   // z: fp16-only residual state
__device__ __align__(256) __half g_hh [(size_t)TT * EMB];
#define WT_EGGC(blk, w) (((size_t)(blk) * 5 + (w)) * 65536)
#define WT_ANG  ((size_t)60 * 65536)
#define WT_EDGE (WT_ANG + 16384)
__device__ __align__(256) __half g_wh [WT_EDGE + 16384];

// ---------------- helpers ----------------
__device__ __forceinline__ float fsig(float x)  { return __frcp_rn(1.f + __expf(-x)); }
__device__ __forceinline__ float fsilu(float x) { return x * fsig(x); }
__device__ __forceinline__ uint32_t h2u(__half2 h) { return *(uint32_t*)&h; }

__device__ __forceinline__ void unpack8(uint4 u, float f[8]) {
    __half2 h;
    h = *(__half2*)&u.x; f[0] = __low2float(h); f[1] = __high2float(h);
    h = *(__half2*)&u.y; f[2] = __low2float(h); f[3] = __high2float(h);
    h = *(__half2*)&u.z; f[4] = __low2float(h); f[5] = __high2float(h);
    h = *(__half2*)&u.w; f[6] = __low2float(h); f[7] = __high2float(h);
}
__device__ __forceinline__ uint4 pack8(const float f[8]) {
    uint4 u;
    u.x = h2u(__floats2half2_rn(f[0], f[1]));
    u.y = h2u(__floats2half2_rn(f[2], f[3]));
    u.z = h2u(__floats2half2_rn(f[4], f[5]));
    u.w = h2u(__floats2half2_rn(f[6], f[7]));
    return u;
}

__device__ __forceinline__ void red_add_v4(float* p, float4 v) {
    asm volatile("red.global.add.v4.f32 [%0], {%1,%2,%3,%4};"
                 :: "l"(p), "f"(v.x), "f"(v.y), "f"(v.z), "f"(v.w) : "memory");
}

#define CPA16(dst, src) asm volatile("cp.async.cg.shared.global [%0], [%1], 16;" :: "r"(dst), "l"(src))
#define CPA_COMMIT      asm volatile("cp.async.commit_group;")
#define CPA_WAIT0       asm volatile("cp.async.wait_group 0;")
#define CPA_WAIT1       asm volatile("cp.async.wait_group 1;")

__device__ __forceinline__ void mma_f16(float c[4], const uint32_t a[4], const uint32_t b[2]) {
    asm volatile(
        "mma.sync.aligned.m16n8k16.row.col.f32.f16.f16.f32 "
        "{%0,%1,%2,%3}, {%4,%5,%6,%7}, {%8,%9}, {%0,%1,%2,%3};"
        : "+f"(c[0]), "+f"(c[1]), "+f"(c[2]), "+f"(c[3])
        : "r"(a[0]), "r"(a[1]), "r"(a[2]), "r"(a[3]), "r"(b[0]), "r"(b[1]));
}

// ================= FP16 GEMM, BN = 256 (256 thr, 8 warps, warp tile 64x64) =================
// MODE 0: H[sel] = fp16(acc+bias); optional epilogue zeroing of Z0 (y==0) / Z1 (y==1).
// MODE 1: Cf = silu(LN(acc+bias)) fp32 + fp16 mirror Ch.
// MODE 2: Ch = silu(LN(acc+bias)) fp16 only.
#define ASZH 3072
#define BSZH 6144
#define F16SMEM ((3 * ASZH + 3 * BSZH) * 2)

template <int MODE>
__global__ __launch_bounds__(256, 1)
void f16_gemm256_kernel(const __half* __restrict__ A,
                        const __half* B0, const __half* B1, const __half* B2, const __half* B3,
                        const float* bi0, const float* bi1, const float* bi2, const float* bi3,
                        __half* H0, __half* H1, __half* H2, __half* H3,
                        float* __restrict__ Cf, __half* __restrict__ Ch,
                        const float* __restrict__ lns, const float* __restrict__ lnb,
                        float* __restrict__ Z0, float* __restrict__ Z1,
                        int M, int K) {
    const __half* B; const float* bias; __half* H;
    switch (blockIdx.y) {
        case 0:  B = B0; bias = bi0; H = H0; break;
        case 1:  B = B1; bias = bi1; H = H1; break;
        case 2:  B = B2; bias = bi2; H = H2; break;
        default: B = B3; bias = bi3; H = H3; break;
    }

    extern __shared__ __half hsm[];
    const uint32_t smem_u = (uint32_t)__cvta_generic_to_shared(hsm);

    const int tid = threadIdx.x;
    const int lane = tid & 31;
    const int warp = tid >> 5;
    const int wm = warp & 1;
    const int wn = warp >> 1;
    const int row0 = blockIdx.x * 128;
    const int mbase = wm * 64;
    const int nbase = wn * 64;
    const int g = lane >> 2;
    const int tg = lane & 3;

    const int ar = tid >> 1, ca = tid & 1;
    const int br0 = tid >> 1, cb0 = tid & 1;
    const int br1 = (tid + 256) >> 1, cb1 = tid & 1;

#define LOADSTAGE(st, k0) do {                                                           \
        CPA16(smem_u + (uint32_t)(((st) * ASZH + ar * 24 + ca * 8) * 2),                 \
              A + (size_t)(row0 + ar) * K + (k0) + ca * 8);                              \
        CPA16(smem_u + (uint32_t)((3 * ASZH + (st) * BSZH + br0 * 24 + cb0 * 8) * 2),    \
              B + (size_t)br0 * K + (k0) + cb0 * 8);                                     \
        CPA16(smem_u + (uint32_t)((3 * ASZH + (st) * BSZH + br1 * 24 + cb1 * 8) * 2),    \
              B + (size_t)br1 * K + (k0) + cb1 * 8);                                     \
        CPA_COMMIT;                                                                      \
    } while (0)

    float acc[4][8][4];
    #pragma unroll
    for (int i = 0; i < 4; i++)
        #pragma unroll
        for (int j = 0; j < 8; j++)
            #pragma unroll
            for (int t = 0; t < 4; t++) acc[i][j][t] = 0.f;

    LOADSTAGE(0, 0);
    LOADSTAGE(1, 16);

    int st = 0;
    for (int k0 = 0; k0 < K; k0 += 16) {
        if (k0 + 16 >= K) { CPA_WAIT0; } else { CPA_WAIT1; }
        __syncthreads();
        if (k0 + 32 < K) {
            int nst = st + 2; if (nst >= 3) nst -= 3;
            LOADSTAGE(nst, k0 + 32);
        }
        const __half* aB = hsm + st * ASZH;
        const __half* bB = hsm + 3 * ASZH + st * BSZH;
        uint32_t afr[4][4];
        #pragma unroll
        for (int i = 0; i < 4; i++) {
            int r = mbase + i * 16 + g;
            afr[i][0] = *(const uint32_t*)&aB[r * 24 + 2 * tg];
            afr[i][1] = *(const uint32_t*)&aB[(r + 8) * 24 + 2 * tg];
            afr[i][2] = *(const uint32_t*)&aB[r * 24 + 2 * tg + 8];
            afr[i][3] = *(const uint32_t*)&aB[(r + 8) * 24 + 2 * tg + 8];
        }
        uint32_t bfr[8][2];
        #pragma unroll
        for (int j = 0; j < 8; j++) {
            int n = nbase + j * 8 + g;
            bfr[j][0] = *(const uint32_t*)&bB[n * 24 + 2 * tg];
            bfr[j][1] = *(const uint32_t*)&bB[n * 24 + 2 * tg + 8];
        }
        #pragma unroll
        for (int i = 0; i < 4; i++)
            #pragma unroll
            for (int j = 0; j < 8; j++)
                mma_f16(acc[i][j], afr[i], bfr[j]);
        st++; if (st >= 3) st = 0;
    }
#undef LOADSTAGE

    // bias add
    #pragma unroll
    for (int j = 0; j < 8; j++) {
        int c = nbase + j * 8 + 2 * tg;
        float2 bb = *(const float2*)&bias[c];
        #pragma unroll
        for (int i = 0; i < 4; i++) {
            acc[i][j][0] += bb.x; acc[i][j][1] += bb.y;
            acc[i][j][2] += bb.x; acc[i][j][3] += bb.y;
        }
    }

    if (MODE == 0) {
        #pragma unroll
        for (int j = 0; j < 8; j++) {
            int c = nbase + j * 8 + 2 * tg;
            #pragma unroll
            for (int i = 0; i < 4; i++) {
                int r = row0 + mbase + i * 16 + g;
                *(uint32_t*)&H[(size_t)r * 256 + c] = h2u(__floats2half2_rn(acc[i][j][0], acc[i][j][1]));
                *(uint32_t*)&H[(size_t)(r + 8) * 256 + c] = h2u(__floats2half2_rn(acc[i][j][2], acc[i][j][3]));
            }
        }
        float* Z = (blockIdx.y == 0) ? Z0 : ((blockIdx.y == 1) ? Z1 : nullptr);
        if (Z) {
            float4* zrow = (float4*)(Z + (size_t)row0 * 256);
            float4 zv = make_float4(0.f, 0.f, 0.f, 0.f);
            #pragma unroll
            for (int i = 0; i < 32; i++) zrow[tid + i * 256] = zv;
        }
    } else {
        // fused LayerNorm + SiLU
        __syncthreads();
        float* part = (float*)hsm;
        float s1[8], s2[8];
        #pragma unroll
        for (int k = 0; k < 8; k++) { s1[k] = 0.f; s2[k] = 0.f; }
        #pragma unroll
        for (int i = 0; i < 4; i++)
            #pragma unroll
            for (int j = 0; j < 8; j++) {
                float a0 = acc[i][j][0], a1 = acc[i][j][1];
                float a2 = acc[i][j][2], a3 = acc[i][j][3];
                s1[2 * i] += a0 + a1;       s2[2 * i] += a0 * a0 + a1 * a1;
                s1[2 * i + 1] += a2 + a3;   s2[2 * i + 1] += a2 * a2 + a3 * a3;
            }
        #pragma unroll
        for (int off = 1; off <= 2; off <<= 1)
            #pragma unroll
            for (int k = 0; k < 8; k++) {
                s1[k] += __shfl_xor_sync(0xffffffffu, s1[k], off);
                s2[k] += __shfl_xor_sync(0xffffffffu, s2[k], off);
            }
        if (tg == 0) {
            #pragma unroll
            for (int i = 0; i < 4; i++) {
                int r = mbase + i * 16 + g;
                part[(wn * 128 + r) * 2 + 0] = s1[2 * i];
                part[(wn * 128 + r) * 2 + 1] = s2[2 * i];
                part[(wn * 128 + r + 8) * 2 + 0] = s1[2 * i + 1];
                part[(wn * 128 + r + 8) * 2 + 1] = s2[2 * i + 1];
            }
        }
        __syncthreads();
        float mu[8], inv[8];
        #pragma unroll
        for (int i = 0; i < 4; i++)
            #pragma unroll
            for (int h = 0; h < 2; h++) {
                int r = mbase + i * 16 + g + h * 8;
                float S1 = 0.f, S2 = 0.f;
                #pragma unroll
                for (int w = 0; w < 4; w++) {
                    S1 += part[(w * 128 + r) * 2 + 0];
                    S2 += part[(w * 128 + r) * 2 + 1];
                }
                float m = S1 * (1.f / 256.f);
                float v = S2 * (1.f / 256.f) - m * m;
                mu[2 * i + h] = m;
                inv[2 * i + h] = rsqrtf(v + 1e-5f);
            }
        #pragma unroll
        for (int j = 0; j < 8; j++) {
            int c = nbase + j * 8 + 2 * tg;
            float2 sc = *(const float2*)&lns[c];
            float2 sb = *(const float2*)&lnb[c];
            #pragma unroll
            for (int i = 0; i < 4; i++) {
                #pragma unroll
                for (int h = 0; h < 2; h++) {
                    int r = row0 + mbase + i * 16 + g + h * 8;
                    float o0 = fsilu((acc[i][j][2 * h] - mu[2 * i + h]) * inv[2 * i + h] * sc.x + sb.x);
                    float o1 = fsilu((acc[i][j][2 * h + 1] - mu[2 * i + h]) * inv[2 * i + h] * sc.y + sb.y);
                    if (MODE == 1)
                        *(float2*)&Cf[(size_t)r * 256 + c] = make_float2(o0, o1);
                    *(uint32_t*)&Ch[(size_t)r * 256 + c] = h2u(__floats2half2_rn(o0, o1));
                }
            }
        }
    }
}

// ---------------- weight convert + transpose ----------------
__global__ void wconv_kernel(const float* __restrict__ in, __half* __restrict__ out,
                             int K, int N) {
    __shared__ float t[32][33];
    const float* src = in + (size_t)blockIdx.z * K * N;
    __half* dst = out + (size_t)blockIdx.z * K * N;
    int k0 = blockIdx.x * 32, n0 = blockIdx.y * 32;
    int tx = threadIdx.x, ty = threadIdx.y;
    #pragma unroll
    for (int i = 0; i < 4; i++)
        t[ty + 8 * i][tx] = src[(size_t)(k0 + ty + 8 * i) * N + n0 + tx];
    __syncthreads();
    #pragma unroll
    for (int i = 0; i < 4; i++)
        dst[(size_t)(n0 + ty + 8 * i) * K + k0 + tx] = __float2half(t[tx][ty + 8 * i]);
}

// ---------------- fp32 SGEMM (odd shapes); mode1: fused LN+SiLU, fp16-only out ----------------
__global__ void sgemm_bias_kernel(const float* __restrict__ A, const float* __restrict__ B,
                                  const float* __restrict__ bias, float* __restrict__ C,
                                  __half* __restrict__ Ch,
                                  int M, int N, int K,
                                  const float* __restrict__ lns, const float* __restrict__ lnb,
                                  int mode) {
    __shared__ float As[16][64];
    __shared__ float Bs[16][64];
    const int tid = threadIdx.x;
    const int tcol = tid & 15;
    const int trow = tid >> 4;
    const int row0 = blockIdx.y * 64;
    const int col0 = blockIdx.x * 64;

    float acc[4][4] = {};
    for (int k0 = 0; k0 < K; k0 += 16) {
        #pragma unroll
        for (int i = 0; i < 4; i++) {
            int idx = tid + i * 256;
            int m = idx >> 4, kk = idx & 15;
            int gk = k0 + kk;
            As[kk][m] = (gk < K) ? A[(size_t)(row0 + m) * K + gk] : 0.f;
        }
        #pragma unroll
        for (int i = 0; i < 4; i++) {
            int idx = tid + i * 256;
            int kk = idx >> 6, n = idx & 63;
            int gk = k0 + kk;
            Bs[kk][n] = (gk < K) ? B[(size_t)gk * N + (col0 + n)] : 0.f;
        }
        __syncthreads();
        #pragma unroll
        for (int kk = 0; kk < 16; kk++) {
            float a[4], b[4];
            #pragma unroll
            for (int i = 0; i < 4; i++) a[i] = As[kk][trow * 4 + i];
            #pragma unroll
            for (int j = 0; j < 4; j++) b[j] = Bs[kk][tcol * 4 + j];
            #pragma unroll
            for (int i = 0; i < 4; i++)
                #pragma unroll
                for (int j = 0; j < 4; j++) acc[i][j] += a[i] * b[j];
        }
        __syncthreads();
    }
    #pragma unroll
    for (int j = 0; j < 4; j++) {
        float bv = bias[col0 + tcol * 4 + j];
        #pragma unroll
        for (int i = 0; i < 4; i++) acc[i][j] += bv;
    }
    if (mode == 0) {
        #pragma unroll
        for (int i = 0; i < 4; i++) {
            int r = row0 + trow * 4 + i;
            #pragma unroll
            for (int j = 0; j < 4; j++)
                C[(size_t)r * N + col0 + tcol * 4 + j] = acc[i][j];
        }
    } else {
        #pragma unroll
        for (int i = 0; i < 4; i++) {
            float rs = acc[i][0] + acc[i][1] + acc[i][2] + acc[i][3];
            float rq = acc[i][0] * acc[i][0] + acc[i][1] * acc[i][1] +
                       acc[i][2] * acc[i][2] + acc[i][3] * acc[i][3];
            #pragma unroll
            for (int o = 1; o <= 8; o <<= 1) {
                rs += __shfl_xor_sync(0xffffffffu, rs, o);
                rq += __shfl_xor_sync(0xffffffffu, rq, o);
            }
            float mval = rs * (1.f / 64.f);
            float vval = rq * (1.f / 64.f) - mval * mval;
            float inv = rsqrtf(vval + 1e-5f);
            int r = row0 + trow * 4 + i;
            int c = tcol * 4;
            float o0 = fsilu((acc[i][0] - mval) * inv * lns[c + 0] + lnb[c + 0]);
            float o1 = fsilu((acc[i][1] - mval) * inv * lns[c + 1] + lnb[c + 1]);
            float o2 = fsilu((acc[i][2] - mval) * inv * lns[c + 2] + lnb[c + 2]);
            float o3 = fsilu((acc[i][3] - mval) * inv * lns[c + 3] + lnb[c + 3]);
            uint2 u;
            u.x = h2u(__floats2half2_rn(o0, o1));
            u.y = h2u(__floats2half2_rn(o2, o3));
            *(uint2*)&Ch[(size_t)r * 64 + c] = u;
        }
    }
}

// ---------------- LayerNorm + SiLU (warp per row) + fp16 mirror ----------------
__global__ void ln_silu_kernel(const float* __restrict__ in, const float* __restrict__ s,
                               const float* __restrict__ b, float* __restrict__ out,
                               __half* __restrict__ outh, int M, int Hd) {
    int row = blockIdx.x * (blockDim.x >> 5) + (threadIdx.x >> 5);
    if (row >= M) return;
    int lane = threadIdx.x & 31;
    int per = Hd >> 5;
    float v[8];
    const float* rin = in + (size_t)row * Hd;
    float sum = 0.f;
    for (int i = 0; i < per; i++) { v[i] = rin[lane + i * 32]; sum += v[i]; }
    #pragma unroll
    for (int o = 16; o; o >>= 1) sum += __shfl_xor_sync(0xffffffffu, sum, o);
    float mu = sum / Hd;
    float vs = 0.f;
    for (int i = 0; i < per; i++) { float d = v[i] - mu; vs += d * d; }
    #pragma unroll
    for (int o = 16; o; o >>= 1) vs += __shfl_xor_sync(0xffffffffu, vs, o);
    float inv = rsqrtf(vs / Hd + 1e-5f);
    float* rout = out + (size_t)row * Hd;
    __half* hout = outh + (size_t)row * Hd;
    for (int i = 0; i < per; i++) {
        int c = lane + i * 32;
        float t = (v[i] - mu) * inv * s[c] + b[c];
        float sl = fsilu(t);
        rout[c] = sl;
        hout[c] = __float2half(sl);
    }
}

// ---------------- EGGC node update ----------------
__global__ void node_update_kernel(const __half* __restrict__ g3, const float* __restrict__ sumsh,
                                   const float* __restrict__ sums, const float* __restrict__ s,
                                   const float* __restrict__ b, float* __restrict__ x,
                                   __half* __restrict__ xh, int M) {
    int row = blockIdx.x * 8 + (threadIdx.x >> 5);
    if (row >= M) return;
    int lane = threadIdx.x & 31;
    size_t base = (size_t)row * HH;
    float v[8];
    float sum = 0.f;
    #pragma unroll
    for (int i = 0; i < 8; i++) {
        int c = lane + i * 32;
        float val = __half2float(g3[base + c]) + sumsh[base + c] / (sums[base + c] + 1e-6f);
        v[i] = val; sum += val;
    }
    #pragma unroll
    for (int o = 16; o; o >>= 1) sum += __shfl_xor_sync(0xffffffffu, sum, o);
    float mu = sum / HH;
    float vs = 0.f;
    #pragma unroll
    for (int i = 0; i < 8; i++) { float d = v[i] - mu; vs += d * d; }
    #pragma unroll
    for (int o = 16; o; o >>= 1) vs += __shfl_xor_sync(0xffffffffu, vs, o);
    float inv = rsqrtf(vs / HH + 1e-5f);
    #pragma unroll
    for (int i = 0; i < 8; i++) {
        int c = lane + i * 32;
        float t = (v[i] - mu) * inv * s[c] + b[c];
        float nv = x[base + c] + fsilu(t);
        x[base + c] = nv;
        xh[base + c] = __float2half(nv);
    }
}

// ---------------- fused EGGC message + segment sums + edge LN/SiLU residual ----------------
// EDGE16=0: edge residual in fp32 edgef + fp16 mirror.  EDGE16=1: fp16-only edgefh.
template <int EDGE16>
__global__ void eggc_msg_ln_kernel(const uint4* __restrict__ g0, const uint4* __restrict__ g1,
                                   const uint4* __restrict__ g4, const uint4* __restrict__ m,
                                   const int* __restrict__ src, const int* __restrict__ dst,
                                   float* __restrict__ sum_s, float* __restrict__ sum_sh,
                                   const float4* __restrict__ lns, const float4* __restrict__ lnb,
                                   float4* __restrict__ edgef, __half* __restrict__ edgefh, int Ecnt) {
    int e = blockIdx.x * 8 + (threadIdx.x >> 5);
    if (e >= Ecnt) return;
    int lane = threadIdx.x & 31;
    int s = src[e], d = dst[e];

    float m8[8], a8[8], b8[8], u8[8];
    unpack8(m[(size_t)e * 32 + lane], m8);
    unpack8(g0[(size_t)s * 32 + lane], a8);
    unpack8(g1[(size_t)d * 32 + lane], b8);
    unpack8(g4[(size_t)s * 32 + lane], u8);

    float mv[8], sg[8];
    #pragma unroll
    for (int k = 0; k < 8; k++) {
        mv[k] = m8[k] + a8[k] + b8[k];
        sg[k] = fsig(mv[k]);
    }

    float* ps  = sum_s  + (size_t)d * HH + lane * 8;
    float* psh = sum_sh + (size_t)d * HH + lane * 8;
    red_add_v4(ps,     make_float4(sg[0], sg[1], sg[2], sg[3]));
    red_add_v4(ps + 4, make_float4(sg[4], sg[5], sg[6], sg[7]));
    red_add_v4(psh,     make_float4(u8[0] * sg[0], u8[1] * sg[1], u8[2] * sg[2], u8[3] * sg[3]));
    red_add_v4(psh + 4, make_float4(u8[4] * sg[4], u8[5] * sg[5], u8[6] * sg[6], u8[7] * sg[7]));

    float sum = 0.f;
    #pragma unroll
    for (int k = 0; k < 8; k++) sum += mv[k];
    #pragma unroll
    for (int o = 16; o; o >>= 1) sum += __shfl_xor_sync(0xffffffffu, sum, o);
    float mu = sum * (1.f / 256.f);
    float vs = 0.f;
    #pragma unroll
    for (int k = 0; k < 8; k++) { float dd = mv[k] - mu; vs += dd * dd; }
    #pragma unroll
    for (int o = 16; o; o >>= 1) vs += __shfl_xor_sync(0xffffffffu, vs, o);
    float inv = rsqrtf(vs * (1.f / 256.f) + 1e-5f);

    float4 sc0 = lns[lane * 2], sc1 = lns[lane * 2 + 1];
    float4 bb0 = lnb[lane * 2], bb1 = lnb[lane * 2 + 1];
    float upd[8];
    {
        float scf[8] = {sc0.x, sc0.y, sc0.z, sc0.w, sc1.x, sc1.y, sc1.z, sc1.w};
        float sbf[8] = {bb0.x, bb0.y, bb0.z, bb0.w, bb1.x, bb1.y, bb1.z, bb1.w};
        #pragma unroll
        for (int k = 0; k < 8; k++)
            upd[k] = fsilu((mv[k] - mu) * inv * scf[k] + sbf[k]);
    }

    if (EDGE16) {
        uint4* eh = (uint4*)&edgefh[(size_t)e * 256 + lane * 8];
        float ef[8];
        unpack8(*eh, ef);
        #pragma unroll
        for (int k = 0; k < 8; k++) ef[k] += upd[k];
        *eh = pack8(ef);
    } else {
        size_t mb = (size_t)e * 64 + lane * 2;
        float4 ef0 = edgef[mb], ef1 = edgef[mb + 1];
        ef0.x += upd[0]; ef0.y += upd[1]; ef0.z += upd[2]; ef0.w += upd[3];
        ef1.x += upd[4]; ef1.y += upd[5]; ef1.z += upd[6]; ef1.w += upd[7];
        edgef[mb] = ef0;
        edgef[mb + 1] = ef1;
        float ef[8] = {ef0.x, ef0.y, ef0.z, ef0.w, ef1.x, ef1.y, ef1.z, ef1.w};
        *(uint4*)&edgefh[(size_t)e * 256 + lane * 8] = pack8(ef);
    }
}

// ---------------- geometry + RBF (coalesced elementwise forms) ----------------
__global__ void cos_kernel(const float* __restrict__ r, const int* __restrict__ lsrc,
                           const int* __restrict__ ldst, float* __restrict__ out, int Tcnt) {
    int t = blockIdx.x * blockDim.x + threadIdx.x;
    if (t >= Tcnt) return;
    int a = lsrc[t], b = ldst[t];
    float ax = r[(size_t)a * 3 + 0], ay = r[(size_t)a * 3 + 1], az = r[(size_t)a * 3 + 2];
    float bx = r[(size_t)b * 3 + 0], by = r[(size_t)b * 3 + 1], bz = r[(size_t)b * 3 + 2];
    float dot = -(ax * bx + ay * by + az * bz);
    float na = sqrtf(ax * ax + ay * ay + az * az);
    float nb = sqrtf(bx * bx + by * by + bz * bz);
    float c = dot / (na * nb);
    out[t] = fminf(1.f, fmaxf(-1.f, c));
}

__global__ void bondlen_kernel(const float* __restrict__ r, float* __restrict__ out, int Ecnt) {
    int e = blockIdx.x * blockDim.x + threadIdx.x;
    if (e >= Ecnt) return;
    float x = r[(size_t)e * 3 + 0], y = r[(size_t)e * 3 + 1], z = r[(size_t)e * 3 + 2];
    out[e] = sqrtf(x * x + y * y + z * z);
}

__global__ void rbf_kernel(const float* __restrict__ vals, float* __restrict__ out,
                           long long M, int bins, float vmin, float vmax) {
    long long idx = (long long)blockIdx.x * blockDim.x + threadIdx.x;
    long long total = M * bins;
    if (idx >= total) return;
    long long t = idx / bins;
    int k = (int)(idx % bins);
    float spacing = (vmax - vmin) / (bins - 1);
    float center = vmin + k * spacing;
    float gamma = 1.f / spacing;
    float d = vals[t] - center;
    out[idx] = __expf(-gamma * d * d);
}

// ---------------- output head ----------------
__global__ void fc_kernel(const float* __restrict__ x, const float* __restrict__ W,
                          const float* __restrict__ b, float* __restrict__ out) {
    int atom = blockIdx.x * 8 + (threadIdx.x >> 5);
    if (atom >= NN) return;
    int lane = threadIdx.x & 31;
    float sum = 0.f;
    #pragma unroll
    for (int i = 0; i < 8; i++) {
        int c = lane + i * 32;
        sum += x[(size_t)atom * HH + c] * W[c];
    }
    #pragma unroll
    for (int o = 16; o; o >>= 1) sum += __shfl_xor_sync(0xffffffffu, sum, o);
    if (lane == 0) out[1 + atom] = sum + b[0];
}

__global__ void mean_kernel(float* out) {
    __shared__ float sh[32];
    float s = 0.f;
    for (int i = threadIdx.x; i < NN; i += 1024) s += out[1 + i];
    #pragma unroll
    for (int o = 16; o; o >>= 1) s += __shfl_xor_sync(0xffffffffu, s, o);
    if ((threadIdx.x & 31) == 0) sh[threadIdx.x >> 5] = s;
    __syncthreads();
    if (threadIdx.x < 32) {
        s = sh[threadIdx.x];
        #pragma unroll
        for (int o = 16; o; o >>= 1) s += __shfl_xor_sync(0xffffffffu, s, o);
        if (threadIdx.x == 0) out[0] = s / (float)NN;
    }
}

extern "C" void kernel_launch(void* const* d_in, const int* in_sizes, int n_in,
                              void* d_out, int out_size) {
    const float* atom_features = (const float*)d_in[0];
    const float* r    = (const float*)d_in[1];
    const int*   src  = (const int*)d_in[2];
    const int*   dst  = (const int*)d_in[3];
    const int*   lsrc = (const int*)d_in[4];
    const int*   ldst = (const int*)d_in[5];
    const float* atom_W    = (const float*)d_in[6];
    const float* atom_b    = (const float*)d_in[7];
    const float* atom_ln_s = (const float*)d_in[8];
    const float* atom_ln_b = (const float*)d_in[9];
    const float* edge_W1    = (const float*)d_in[10];
    const float* edge_b1    = (const float*)d_in[11];
    const float* edge_ln1_s = (const float*)d_in[12];
    const float* edge_ln1_b = (const float*)d_in[13];
    const float* edge_W2    = (const float*)d_in[14];
    const float* edge_b2    = (const float*)d_in[15];
    const float* edge_ln2_s = (const float*)d_in[16];
    const float* edge_ln2_b = (const float*)d_in[17];
    const float* ang_W1    = (const float*)d_in[18];
    const float* ang_b1    = (const float*)d_in[19];
    const float* ang_ln1_s = (const float*)d_in[20];
    const float* ang_ln1_b = (const float*)d_in[21];
    const float* ang_W2    = (const float*)d_in[22];
    const float* ang_b2    = (const float*)d_in[23];
    const float* ang_ln2_s = (const float*)d_in[24];
    const float* ang_ln2_b = (const float*)d_in[25];
    const float* eggc_W    = (const float*)d_in[26];
    const float* eggc_b    = (const float*)d_in[27];
    const float* eggc_ln_s = (const float*)d_in[28];
    const float* eggc_ln_b = (const float*)d_in[29];
    const float* fc_W = (const float*)d_in[30];
    const float* fc_b = (const float*)d_in[31];
    float* out = (float*)d_out;

    float *px, *py, *psums, *psumsh, *prbf, *pval;
    __half *hg0, *hg1, *hg3, *hg4, *hm;
    __half *hx, *hy, *hz, *hh, *wh;
    cudaGetSymbolAddress((void**)&px,    g_x);
    cudaGetSymbolAddress((void**)&py,    g_y);
    cudaGetSymbolAddress((void**)&psums, g_sums);
    cudaGetSymbolAddress((void**)&psumsh,g_sumsh);
    cudaGetSymbolAddress((void**)&prbf,  g_rbf);
    cudaGetSymbolAddress((void**)&pval,  g_val);
    cudaGetSymbolAddress((void**)&hg0,   g_hg0);
    cudaGetSymbolAddress((void**)&hg1,   g_hg1);
    cudaGetSymbolAddress((void**)&hg3,   g_hg3);
    cudaGetSymbolAddress((void**)&hg4,   g_hg4);
    cudaGetSymbolAddress((void**)&hm,    g_hm);
    cudaGetSymbolAddress((void**)&hx,    g_hx);
    cudaGetSymbolAddress((void**)&hy,    g_hy);
    cudaGetSymbolAddress((void**)&hz,    g_hz);
    cudaGetSymbolAddress((void**)&hh,    g_hh);
    cudaGetSymbolAddress((void**)&wh,    g_wh);

    cudaFuncSetAttribute(f16_gemm256_kernel<0>, cudaFuncAttributeMaxDynamicSharedMemorySize, F16SMEM);
    cudaFuncSetAttribute(f16_gemm256_kernel<1>, cudaFuncAttributeMaxDynamicSharedMemorySize, F16SMEM);
    cudaFuncSetAttribute(f16_gemm256_kernel<2>, cudaFuncAttributeMaxDynamicSharedMemorySize, F16SMEM);

    // ---- convert + transpose weights to fp16 [N,K] ----
    {
        dim3 tb(32, 8);
        wconv_kernel<<<dim3(8, 8, 60), tb>>>(eggc_W, wh, 256, 256);
        wconv_kernel<<<dim3(2, 8, 1), tb>>>(ang_W2, wh + WT_ANG, 64, 256);
        wconv_kernel<<<dim3(2, 8, 1), tb>>>(edge_W2, wh + WT_EDGE, 64, 256);
    }

    // ---- angle branch: z = fp16-only state ----
    cos_kernel<<<TT / 256, 256>>>(r, lsrc, ldst, pval, TT);
    {
        long long total = (long long)TT * TB;
        rbf_kernel<<<(unsigned)((total + 255) / 256), 256>>>(pval, prbf, TT, TB, -1.f, 1.f);
    }
    {
        dim3 grid(1, TT / 64);
        sgemm_bias_kernel<<<grid, 256>>>(prbf, ang_W1, ang_b1, nullptr, hh,
                                         TT, EMB, TB, ang_ln1_s, ang_ln1_b, 1);
    }
    {
        dim3 grid(TT / 128, 1);
        f16_gemm256_kernel<2><<<grid, 256, F16SMEM>>>(
            hh, wh + WT_ANG, wh + WT_ANG, wh + WT_ANG, wh + WT_ANG,
            ang_b2, ang_b2, ang_b2, ang_b2,
            nullptr, nullptr, nullptr, nullptr,
            nullptr, hz, ang_ln2_s, ang_ln2_b, nullptr, nullptr, TT, EMB);
    }

    // ---- edge branch: y fp32 + fp16 mirror ----
    bondlen_kernel<<<EE / 256, 256>>>(r, pval, EE);
    {
        long long total = (long long)EE * EB;
        rbf_kernel<<<(unsigned)((total + 255) / 256), 256>>>(pval, prbf, EE, EB, 0.f, 8.f);
    }
    {
        dim3 grid(1, EE / 64);
        sgemm_bias_kernel<<<grid, 256>>>(prbf, edge_W1, edge_b1, nullptr, hh,
                                         EE, EMB, EB, edge_ln1_s, edge_ln1_b, 1);
    }
    {
        dim3 grid(EE / 128, 1);
        f16_gemm256_kernel<1><<<grid, 256, F16SMEM>>>(
            hh, wh + WT_EDGE, wh + WT_EDGE, wh + WT_EDGE, wh + WT_EDGE,
            edge_b2, edge_b2, edge_b2, edge_b2,
            nullptr, nullptr, nullptr, nullptr,
            py, hy, edge_ln2_s, edge_ln2_b, nullptr, nullptr, EE, EMB);
    }

    // ---- atom branch ----
    {
        dim3 grid(HH / 64, NN / 64);
        sgemm_bias_kernel<<<grid, 256>>>(atom_features, atom_W, atom_b, px, nullptr,
                                         NN, HH, AIN, nullptr, nullptr, 0);
    }
    ln_silu_kernel<<<NN / 8, 256>>>(px, atom_ln_s, atom_ln_b, px, hx, NN, HH);

    // ---- 12 EGGC blocks ----
    for (int blk = 0; blk < 12; blk++) {
        bool line = (blk < 8) && (blk & 1);
        float* nodef = line ? py : px;
        __half* nodeh = line ? hy : hx;
        int n        = line ? EE : NN;
        __half* edgeh = line ? hz : hy;
        int e        = line ? TT : EE;
        const int* gs = line ? lsrc : src;
        const int* gd = line ? ldst : dst;
        const float* bb = eggc_b   + (size_t)blk * 5 * HH;
        const float* ls = eggc_ln_s + (size_t)blk * 2 * HH;
        const float* lb = eggc_ln_b + (size_t)blk * 2 * HH;

        // 4 node-side GEMMs in one launch (shared A); also zeros psums (y=0) and psumsh (y=1)
        {
            dim3 grid(n / 128, 4);
            f16_gemm256_kernel<0><<<grid, 256, F16SMEM>>>(
                nodeh,
                wh + WT_EGGC(blk, 0), wh + WT_EGGC(blk, 1), wh + WT_EGGC(blk, 3), wh + WT_EGGC(blk, 4),
                bb + 0 * HH, bb + 1 * HH, bb + 3 * HH, bb + 4 * HH,
                hg0, hg1, hg3, hg4,
                nullptr, nullptr, nullptr, nullptr,
                psums, psumsh, n, HH);
        }
        // edge gate GEMM -> hm (fp16)
        {
            dim3 grid(e / 128, 1);
            f16_gemm256_kernel<0><<<grid, 256, F16SMEM>>>(
                edgeh,
                wh + WT_EGGC(blk, 2), wh + WT_EGGC(blk, 2), wh + WT_EGGC(blk, 2), wh + WT_EGGC(blk, 2),
                bb + 2 * HH, bb + 2 * HH, bb + 2 * HH, bb + 2 * HH,
                hm, hm, hm, hm,
                nullptr, nullptr, nullptr, nullptr,
                nullptr, nullptr, e, HH);
        }

        if (line) {
            eggc_msg_ln_kernel<1><<<e / 8, 256>>>((const uint4*)hg0, (const uint4*)hg1,
                                                  (const uint4*)hg4, (const uint4*)hm,
                                                  gs, gd, psums, psumsh,
                                                  (const float4*)(ls + HH), (const float4*)(lb + HH),
                                                  nullptr, hz, e);
        } else {
            eggc_msg_ln_kernel<0><<<e / 8, 256>>>((const uint4*)hg0, (const uint4*)hg1,
                                                  (const uint4*)hg4, (const uint4*)hm,
                                                  gs, gd, psums, psumsh,
                                                  (const float4*)(ls + HH), (const float4*)(lb + HH),
                                                  (float4*)py, hy, e);
        }

        node_update_kernel<<<(n + 7) / 8, 256>>>(hg3, psumsh, psums, ls, lb, nodef, nodeh, n);
    }

    // ---- output head ----
    fc_kernel<<<(NN + 7) / 8, 256>>>(px, fc_W, fc_b, out);
    mean_kernel<<<1, 1024>>>(out);
}

// round 17
// speedup vs baseline: 1.5145x; 1.0616x over previous
#include <cuda_runtime.h>
#include <cuda_fp16.h>
#include <math.h>
#include <stdint.h>

// ---------------- problem sizes ----------------
#define NN 4096
#define EE 49152
#define TT 262144
#define HH 256
#define EMB 64
#define AIN 92
#define EB 80
#define TB 40

// ---------------- device scratch (allocation-free) ----------------
__device__ float g_x   [(size_t)NN * HH];
__device__ float g_sums[(size_t)EE * HH];
__device__ float g_sumsh[(size_t)EE * HH];
__device__ float g_rbf [(size_t)TT * TB];
__device__ float g_val [(size_t)TT];

// fp16 gate/message buffers
__device__ __align__(256) __half g_hg0[(size_t)EE * HH];
__device__ __align__(256) __half g_hg1[(size_t)EE * HH];
__device__ __align__(256) __half g_hg3[(size_t)EE * HH];
__device__ __align__(256) __half g_hg4[(size_t)EE * HH];
__device__ __align__(256) __half g_hm [(size_t)TT * HH];

// fp16 states + converted weights  (y and z are fp16-only residual state; x keeps fp32 + mirror)
__device__ __align__(256) __half g_hx [(size_t)NN * HH];
__device__ __align__(256) __half g_hy [(size_t)EE * HH];
__device__ __align__(256) __half g_hz [(size_t)TT * HH];
__device__ __align__(256) __half g_hh [(size_t)TT * EMB];
#define WT_EGGC(blk, w) (((size_t)(blk) * 5 + (w)) * 65536)
#define WT_ANG  ((size_t)60 * 65536)
#define WT_EDGE (WT_ANG + 16384)
__device__ __align__(256) __half g_wh [WT_EDGE + 16384];

// ---------------- helpers ----------------
__device__ __forceinline__ float fsig(float x)  { return __frcp_rn(1.f + __expf(-x)); }
__device__ __forceinline__ float fsilu(float x) { return x * fsig(x); }
__device__ __forceinline__ uint32_t h2u(__half2 h) { return *(uint32_t*)&h; }

__device__ __forceinline__ void unpack8(uint4 u, float f[8]) {
    __half2 h;
    h = *(__half2*)&u.x; f[0] = __low2float(h); f[1] = __high2float(h);
    h = *(__half2*)&u.y; f[2] = __low2float(h); f[3] = __high2float(h);
    h = *(__half2*)&u.z; f[4] = __low2float(h); f[5] = __high2float(h);
    h = *(__half2*)&u.w; f[6] = __low2float(h); f[7] = __high2float(h);
}
__device__ __forceinline__ uint4 pack8(const float f[8]) {
    uint4 u;
    u.x = h2u(__floats2half2_rn(f[0], f[1]));
    u.y = h2u(__floats2half2_rn(f[2], f[3]));
    u.z = h2u(__floats2half2_rn(f[4], f[5]));
    u.w = h2u(__floats2half2_rn(f[6], f[7]));
    return u;
}

__device__ __forceinline__ void red_add_v4(float* p, float4 v) {
    asm volatile("red.global.add.v4.f32 [%0], {%1,%2,%3,%4};"
                 :: "l"(p), "f"(v.x), "f"(v.y), "f"(v.z), "f"(v.w) : "memory");
}

#define CPA16(dst, src) asm volatile("cp.async.cg.shared.global [%0], [%1], 16;" :: "r"(dst), "l"(src))
#define CPA_COMMIT      asm volatile("cp.async.commit_group;")
#define CPA_WAIT0       asm volatile("cp.async.wait_group 0;")
#define CPA_WAIT1       asm volatile("cp.async.wait_group 1;")

__device__ __forceinline__ void mma_f16(float c[4], const uint32_t a[4], const uint32_t b[2]) {
    asm volatile(
        "mma.sync.aligned.m16n8k16.row.col.f32.f16.f16.f32 "
        "{%0,%1,%2,%3}, {%4,%5,%6,%7}, {%8,%9}, {%0,%1,%2,%3};"
        : "+f"(c[0]), "+f"(c[1]), "+f"(c[2]), "+f"(c[3])
        : "r"(a[0]), "r"(a[1]), "r"(a[2]), "r"(a[3]), "r"(b[0]), "r"(b[1]));
}

// ================= FP16 GEMM, BN = 256 (256 thr, 8 warps, warp tile 64x64) =================
// MODE 0: H[sel] = fp16(acc+bias); optional epilogue zeroing of Z0 (y==0) / Z1 (y==1).
// MODE 1: Cf = silu(LN(acc+bias)) fp32 + fp16 mirror Ch.
// MODE 2: Ch = silu(LN(acc+bias)) fp16 only.
#define ASZH 3072
#define BSZH 6144
#define F16SMEM ((3 * ASZH + 3 * BSZH) * 2)

template <int MODE>
__global__ __launch_bounds__(256, 1)
void f16_gemm256_kernel(const __half* __restrict__ A,
                        const __half* B0, const __half* B1, const __half* B2, const __half* B3,
                        const float* bi0, const float* bi1, const float* bi2, const float* bi3,
                        __half* H0, __half* H1, __half* H2, __half* H3,
                        float* __restrict__ Cf, __half* __restrict__ Ch,
                        const float* __restrict__ lns, const float* __restrict__ lnb,
                        float* __restrict__ Z0, float* __restrict__ Z1,
                        int M, int K) {
    const __half* B; const float* bias; __half* H;
    switch (blockIdx.y) {
        case 0:  B = B0; bias = bi0; H = H0; break;
        case 1:  B = B1; bias = bi1; H = H1; break;
        case 2:  B = B2; bias = bi2; H = H2; break;
        default: B = B3; bias = bi3; H = H3; break;
    }

    extern __shared__ __half hsm[];
    const uint32_t smem_u = (uint32_t)__cvta_generic_to_shared(hsm);

    const int tid = threadIdx.x;
    const int lane = tid & 31;
    const int warp = tid >> 5;
    const int wm = warp & 1;
    const int wn = warp >> 1;
    const int row0 = blockIdx.x * 128;
    const int mbase = wm * 64;
    const int nbase = wn * 64;
    const int g = lane >> 2;
    const int tg = lane & 3;

    const int ar = tid >> 1, ca = tid & 1;
    const int br0 = tid >> 1, cb0 = tid & 1;
    const int br1 = (tid + 256) >> 1, cb1 = tid & 1;

#define LOADSTAGE(st, k0) do {                                                           \
        CPA16(smem_u + (uint32_t)(((st) * ASZH + ar * 24 + ca * 8) * 2),                 \
              A + (size_t)(row0 + ar) * K + (k0) + ca * 8);                              \
        CPA16(smem_u + (uint32_t)((3 * ASZH + (st) * BSZH + br0 * 24 + cb0 * 8) * 2),    \
              B + (size_t)br0 * K + (k0) + cb0 * 8);                                     \
        CPA16(smem_u + (uint32_t)((3 * ASZH + (st) * BSZH + br1 * 24 + cb1 * 8) * 2),    \
              B + (size_t)br1 * K + (k0) + cb1 * 8);                                     \
        CPA_COMMIT;                                                                      \
    } while (0)

    float acc[4][8][4];
    #pragma unroll
    for (int i = 0; i < 4; i++)
        #pragma unroll
        for (int j = 0; j < 8; j++)
            #pragma unroll
            for (int t = 0; t < 4; t++) acc[i][j][t] = 0.f;

    LOADSTAGE(0, 0);
    LOADSTAGE(1, 16);

    int st = 0;
    for (int k0 = 0; k0 < K; k0 += 16) {
        if (k0 + 16 >= K) { CPA_WAIT0; } else { CPA_WAIT1; }
        __syncthreads();
        if (k0 + 32 < K) {
            int nst = st + 2; if (nst >= 3) nst -= 3;
            LOADSTAGE(nst, k0 + 32);
        }
        const __half* aB = hsm + st * ASZH;
        const __half* bB = hsm + 3 * ASZH + st * BSZH;
        uint32_t afr[4][4];
        #pragma unroll
        for (int i = 0; i < 4; i++) {
            int r = mbase + i * 16 + g;
            afr[i][0] = *(const uint32_t*)&aB[r * 24 + 2 * tg];
            afr[i][1] = *(const uint32_t*)&aB[(r + 8) * 24 + 2 * tg];
            afr[i][2] = *(const uint32_t*)&aB[r * 24 + 2 * tg + 8];
            afr[i][3] = *(const uint32_t*)&aB[(r + 8) * 24 + 2 * tg + 8];
        }
        uint32_t bfr[8][2];
        #pragma unroll
        for (int j = 0; j < 8; j++) {
            int n = nbase + j * 8 + g;
            bfr[j][0] = *(const uint32_t*)&bB[n * 24 + 2 * tg];
            bfr[j][1] = *(const uint32_t*)&bB[n * 24 + 2 * tg + 8];
        }
        #pragma unroll
        for (int i = 0; i < 4; i++)
            #pragma unroll
            for (int j = 0; j < 8; j++)
                mma_f16(acc[i][j], afr[i], bfr[j]);
        st++; if (st >= 3) st = 0;
    }
#undef LOADSTAGE

    // bias add
    #pragma unroll
    for (int j = 0; j < 8; j++) {
        int c = nbase + j * 8 + 2 * tg;
        float2 bb = *(const float2*)&bias[c];
        #pragma unroll
        for (int i = 0; i < 4; i++) {
            acc[i][j][0] += bb.x; acc[i][j][1] += bb.y;
            acc[i][j][2] += bb.x; acc[i][j][3] += bb.y;
        }
    }

    if (MODE == 0) {
        #pragma unroll
        for (int j = 0; j < 8; j++) {
            int c = nbase + j * 8 + 2 * tg;
            #pragma unroll
            for (int i = 0; i < 4; i++) {
                int r = row0 + mbase + i * 16 + g;
                *(uint32_t*)&H[(size_t)r * 256 + c] = h2u(__floats2half2_rn(acc[i][j][0], acc[i][j][1]));
                *(uint32_t*)&H[(size_t)(r + 8) * 256 + c] = h2u(__floats2half2_rn(acc[i][j][2], acc[i][j][3]));
            }
        }
        float* Z = (blockIdx.y == 0) ? Z0 : ((blockIdx.y == 1) ? Z1 : nullptr);
        if (Z) {
            float4* zrow = (float4*)(Z + (size_t)row0 * 256);
            float4 zv = make_float4(0.f, 0.f, 0.f, 0.f);
            #pragma unroll
            for (int i = 0; i < 32; i++) zrow[tid + i * 256] = zv;
        }
    } else {
        // fused LayerNorm + SiLU
        __syncthreads();
        float* part = (float*)hsm;
        float s1[8], s2[8];
        #pragma unroll
        for (int k = 0; k < 8; k++) { s1[k] = 0.f; s2[k] = 0.f; }
        #pragma unroll
        for (int i = 0; i < 4; i++)
            #pragma unroll
            for (int j = 0; j < 8; j++) {
                float a0 = acc[i][j][0], a1 = acc[i][j][1];
                float a2 = acc[i][j][2], a3 = acc[i][j][3];
                s1[2 * i] += a0 + a1;       s2[2 * i] += a0 * a0 + a1 * a1;
                s1[2 * i + 1] += a2 + a3;   s2[2 * i + 1] += a2 * a2 + a3 * a3;
            }
        #pragma unroll
        for (int off = 1; off <= 2; off <<= 1)
            #pragma unroll
            for (int k = 0; k < 8; k++) {
                s1[k] += __shfl_xor_sync(0xffffffffu, s1[k], off);
                s2[k] += __shfl_xor_sync(0xffffffffu, s2[k], off);
            }
        if (tg == 0) {
            #pragma unroll
            for (int i = 0; i < 4; i++) {
                int r = mbase + i * 16 + g;
                part[(wn * 128 + r) * 2 + 0] = s1[2 * i];
                part[(wn * 128 + r) * 2 + 1] = s2[2 * i];
                part[(wn * 128 + r + 8) * 2 + 0] = s1[2 * i + 1];
                part[(wn * 128 + r + 8) * 2 + 1] = s2[2 * i + 1];
            }
        }
        __syncthreads();
        float mu[8], inv[8];
        #pragma unroll
        for (int i = 0; i < 4; i++)
            #pragma unroll
            for (int h = 0; h < 2; h++) {
                int r = mbase + i * 16 + g + h * 8;
                float S1 = 0.f, S2 = 0.f;
                #pragma unroll
                for (int w = 0; w < 4; w++) {
                    S1 += part[(w * 128 + r) * 2 + 0];
                    S2 += part[(w * 128 + r) * 2 + 1];
                }
                float m = S1 * (1.f / 256.f);
                float v = S2 * (1.f / 256.f) - m * m;
                mu[2 * i + h] = m;
                inv[2 * i + h] = rsqrtf(v + 1e-5f);
            }
        #pragma unroll
        for (int j = 0; j < 8; j++) {
            int c = nbase + j * 8 + 2 * tg;
            float2 sc = *(const float2*)&lns[c];
            float2 sb = *(const float2*)&lnb[c];
            #pragma unroll
            for (int i = 0; i < 4; i++) {
                #pragma unroll
                for (int h = 0; h < 2; h++) {
                    int r = row0 + mbase + i * 16 + g + h * 8;
                    float o0 = fsilu((acc[i][j][2 * h] - mu[2 * i + h]) * inv[2 * i + h] * sc.x + sb.x);
                    float o1 = fsilu((acc[i][j][2 * h + 1] - mu[2 * i + h]) * inv[2 * i + h] * sc.y + sb.y);
                    if (MODE == 1)
                        *(float2*)&Cf[(size_t)r * 256 + c] = make_float2(o0, o1);
                    *(uint32_t*)&Ch[(size_t)r * 256 + c] = h2u(__floats2half2_rn(o0, o1));
                }
            }
        }
    }
}

// ---------------- weight convert + transpose ----------------
__global__ void wconv_kernel(const float* __restrict__ in, __half* __restrict__ out,
                             int K, int N) {
    __shared__ float t[32][33];
    const float* src = in + (size_t)blockIdx.z * K * N;
    __half* dst = out + (size_t)blockIdx.z * K * N;
    int k0 = blockIdx.x * 32, n0 = blockIdx.y * 32;
    int tx = threadIdx.x, ty = threadIdx.y;
    #pragma unroll
    for (int i = 0; i < 4; i++)
        t[ty + 8 * i][tx] = src[(size_t)(k0 + ty + 8 * i) * N + n0 + tx];
    __syncthreads();
    #pragma unroll
    for (int i = 0; i < 4; i++)
        dst[(size_t)(n0 + ty + 8 * i) * K + k0 + tx] = __float2half(t[tx][ty + 8 * i]);
}

// ---------------- fp32 SGEMM (odd shapes); mode1: fused LN+SiLU, fp16-only out ----------------
__global__ void sgemm_bias_kernel(const float* __restrict__ A, const float* __restrict__ B,
                                  const float* __restrict__ bias, float* __restrict__ C,
                                  __half* __restrict__ Ch,
                                  int M, int N, int K,
                                  const float* __restrict__ lns, const float* __restrict__ lnb,
                                  int mode) {
    __shared__ float As[16][64];
    __shared__ float Bs[16][64];
    const int tid = threadIdx.x;
    const int tcol = tid & 15;
    const int trow = tid >> 4;
    const int row0 = blockIdx.y * 64;
    const int col0 = blockIdx.x * 64;

    float acc[4][4] = {};
    for (int k0 = 0; k0 < K; k0 += 16) {
        #pragma unroll
        for (int i = 0; i < 4; i++) {
            int idx = tid + i * 256;
            int m = idx >> 4, kk = idx & 15;
            int gk = k0 + kk;
            As[kk][m] = (gk < K) ? A[(size_t)(row0 + m) * K + gk] : 0.f;
        }
        #pragma unroll
        for (int i = 0; i < 4; i++) {
            int idx = tid + i * 256;
            int kk = idx >> 6, n = idx & 63;
            int gk = k0 + kk;
            Bs[kk][n] = (gk < K) ? B[(size_t)gk * N + (col0 + n)] : 0.f;
        }
        __syncthreads();
        #pragma unroll
        for (int kk = 0; kk < 16; kk++) {
            float a[4], b[4];
            #pragma unroll
            for (int i = 0; i < 4; i++) a[i] = As[kk][trow * 4 + i];
            #pragma unroll
            for (int j = 0; j < 4; j++) b[j] = Bs[kk][tcol * 4 + j];
            #pragma unroll
            for (int i = 0; i < 4; i++)
                #pragma unroll
                for (int j = 0; j < 4; j++) acc[i][j] += a[i] * b[j];
        }
        __syncthreads();
    }
    #pragma unroll
    for (int j = 0; j < 4; j++) {
        float bv = bias[col0 + tcol * 4 + j];
        #pragma unroll
        for (int i = 0; i < 4; i++) acc[i][j] += bv;
    }
    if (mode == 0) {
        #pragma unroll
        for (int i = 0; i < 4; i++) {
            int r = row0 + trow * 4 + i;
            #pragma unroll
            for (int j = 0; j < 4; j++)
                C[(size_t)r * N + col0 + tcol * 4 + j] = acc[i][j];
        }
    } else {
        #pragma unroll
        for (int i = 0; i < 4; i++) {
            float rs = acc[i][0] + acc[i][1] + acc[i][2] + acc[i][3];
            float rq = acc[i][0] * acc[i][0] + acc[i][1] * acc[i][1] +
                       acc[i][2] * acc[i][2] + acc[i][3] * acc[i][3];
            #pragma unroll
            for (int o = 1; o <= 8; o <<= 1) {
                rs += __shfl_xor_sync(0xffffffffu, rs, o);
                rq += __shfl_xor_sync(0xffffffffu, rq, o);
            }
            float mval = rs * (1.f / 64.f);
            float vval = rq * (1.f / 64.f) - mval * mval;
            float inv = rsqrtf(vval + 1e-5f);
            int r = row0 + trow * 4 + i;
            int c = tcol * 4;
            float o0 = fsilu((acc[i][0] - mval) * inv * lns[c + 0] + lnb[c + 0]);
            float o1 = fsilu((acc[i][1] - mval) * inv * lns[c + 1] + lnb[c + 1]);
            float o2 = fsilu((acc[i][2] - mval) * inv * lns[c + 2] + lnb[c + 2]);
            float o3 = fsilu((acc[i][3] - mval) * inv * lns[c + 3] + lnb[c + 3]);
            uint2 u;
            u.x = h2u(__floats2half2_rn(o0, o1));
            u.y = h2u(__floats2half2_rn(o2, o3));
            *(uint2*)&Ch[(size_t)r * 64 + c] = u;
        }
    }
}

// ---------------- LayerNorm + SiLU (warp per row) + fp16 mirror ----------------
__global__ void ln_silu_kernel(const float* __restrict__ in, const float* __restrict__ s,
                               const float* __restrict__ b, float* __restrict__ out,
                               __half* __restrict__ outh, int M, int Hd) {
    int row = blockIdx.x * (blockDim.x >> 5) + (threadIdx.x >> 5);
    if (row >= M) return;
    int lane = threadIdx.x & 31;
    int per = Hd >> 5;
    float v[8];
    const float* rin = in + (size_t)row * Hd;
    float sum = 0.f;
    for (int i = 0; i < per; i++) { v[i] = rin[lane + i * 32]; sum += v[i]; }
    #pragma unroll
    for (int o = 16; o; o >>= 1) sum += __shfl_xor_sync(0xffffffffu, sum, o);
    float mu = sum / Hd;
    float vs = 0.f;
    for (int i = 0; i < per; i++) { float d = v[i] - mu; vs += d * d; }
    #pragma unroll
    for (int o = 16; o; o >>= 1) vs += __shfl_xor_sync(0xffffffffu, vs, o);
    float inv = rsqrtf(vs / Hd + 1e-5f);
    float* rout = out + (size_t)row * Hd;
    __half* hout = outh + (size_t)row * Hd;
    for (int i = 0; i < per; i++) {
        int c = lane + i * 32;
        float t = (v[i] - mu) * inv * s[c] + b[c];
        float sl = fsilu(t);
        rout[c] = sl;
        hout[c] = __float2half(sl);
    }
}

// ---------------- EGGC node update ----------------
// X16=0: node state fp32 x + fp16 mirror xh.  X16=1: node state fp16-only xh.
template <int X16>
__global__ void node_update_kernel(const __half* __restrict__ g3, const float* __restrict__ sumsh,
                                   const float* __restrict__ sums, const float* __restrict__ s,
                                   const float* __restrict__ b, float* __restrict__ x,
                                   __half* __restrict__ xh, int M) {
    int row = blockIdx.x * 8 + (threadIdx.x >> 5);
    if (row >= M) return;
    int lane = threadIdx.x & 31;
    size_t base = (size_t)row * HH;
    float v[8];
    float sum = 0.f;
    #pragma unroll
    for (int i = 0; i < 8; i++) {
        int c = lane + i * 32;
        float val = __half2float(g3[base + c]) + sumsh[base + c] / (sums[base + c] + 1e-6f);
        v[i] = val; sum += val;
    }
    #pragma unroll
    for (int o = 16; o; o >>= 1) sum += __shfl_xor_sync(0xffffffffu, sum, o);
    float mu = sum / HH;
    float vs = 0.f;
    #pragma unroll
    for (int i = 0; i < 8; i++) { float d = v[i] - mu; vs += d * d; }
    #pragma unroll
    for (int o = 16; o; o >>= 1) vs += __shfl_xor_sync(0xffffffffu, vs, o);
    float inv = rsqrtf(vs / HH + 1e-5f);
    #pragma unroll
    for (int i = 0; i < 8; i++) {
        int c = lane + i * 32;
        float t = (v[i] - mu) * inv * s[c] + b[c];
        float upd = fsilu(t);
        if (X16) {
            float nv = __half2float(xh[base + c]) + upd;
            xh[base + c] = __float2half(nv);
        } else {
            float nv = x[base + c] + upd;
            x[base + c] = nv;
            xh[base + c] = __float2half(nv);
        }
    }
}

// ---------------- fused EGGC message + segment sums + edge LN/SiLU residual (fp16 state) ----------------
__global__ void eggc_msg_ln_kernel(const uint4* __restrict__ g0, const uint4* __restrict__ g1,
                                   const uint4* __restrict__ g4, const uint4* __restrict__ m,
                                   const int* __restrict__ src, const int* __restrict__ dst,
                                   float* __restrict__ sum_s, float* __restrict__ sum_sh,
                                   const float4* __restrict__ lns, const float4* __restrict__ lnb,
                                   __half* __restrict__ edgefh, int Ecnt) {
    int e = blockIdx.x * 8 + (threadIdx.x >> 5);
    if (e >= Ecnt) return;
    int lane = threadIdx.x & 31;
    int s = src[e], d = dst[e];

    float m8[8], a8[8], b8[8], u8[8];
    unpack8(m[(size_t)e * 32 + lane], m8);
    unpack8(g0[(size_t)s * 32 + lane], a8);
    unpack8(g1[(size_t)d * 32 + lane], b8);
    unpack8(g4[(size_t)s * 32 + lane], u8);

    float mv[8], sg[8];
    #pragma unroll
    for (int k = 0; k < 8; k++) {
        mv[k] = m8[k] + a8[k] + b8[k];
        sg[k] = fsig(mv[k]);
    }

    float* ps  = sum_s  + (size_t)d * HH + lane * 8;
    float* psh = sum_sh + (size_t)d * HH + lane * 8;
    red_add_v4(ps,     make_float4(sg[0], sg[1], sg[2], sg[3]));
    red_add_v4(ps + 4, make_float4(sg[4], sg[5], sg[6], sg[7]));
    red_add_v4(psh,     make_float4(u8[0] * sg[0], u8[1] * sg[1], u8[2] * sg[2], u8[3] * sg[3]));
    red_add_v4(psh + 4, make_float4(u8[4] * sg[4], u8[5] * sg[5], u8[6] * sg[6], u8[7] * sg[7]));

    float sum = 0.f;
    #pragma unroll
    for (int k = 0; k < 8; k++) sum += mv[k];
    #pragma unroll
    for (int o = 16; o; o >>= 1) sum += __shfl_xor_sync(0xffffffffu, sum, o);
    float mu = sum * (1.f / 256.f);
    float vs = 0.f;
    #pragma unroll
    for (int k = 0; k < 8; k++) { float dd = mv[k] - mu; vs += dd * dd; }
    #pragma unroll
    for (int o = 16; o; o >>= 1) vs += __shfl_xor_sync(0xffffffffu, vs, o);
    float inv = rsqrtf(vs * (1.f / 256.f) + 1e-5f);

    float4 sc0 = lns[lane * 2], sc1 = lns[lane * 2 + 1];
    float4 bb0 = lnb[lane * 2], bb1 = lnb[lane * 2 + 1];
    float scf[8] = {sc0.x, sc0.y, sc0.z, sc0.w, sc1.x, sc1.y, sc1.z, sc1.w};
    float sbf[8] = {bb0.x, bb0.y, bb0.z, bb0.w, bb1.x, bb1.y, bb1.z, bb1.w};

    uint4* eh = (uint4*)&edgefh[(size_t)e * 256 + lane * 8];
    float ef[8];
    unpack8(*eh, ef);
    #pragma unroll
    for (int k = 0; k < 8; k++)
        ef[k] += fsilu((mv[k] - mu) * inv * scf[k] + sbf[k]);
    *eh = pack8(ef);
}

// ---------------- geometry + RBF (coalesced elementwise forms) ----------------
__global__ void cos_kernel(const float* __restrict__ r, const int* __restrict__ lsrc,
                           const int* __restrict__ ldst, float* __restrict__ out, int Tcnt) {
    int t = blockIdx.x * blockDim.x + threadIdx.x;
    if (t >= Tcnt) return;
    int a = lsrc[t], b = ldst[t];
    float ax = r[(size_t)a * 3 + 0], ay = r[(size_t)a * 3 + 1], az = r[(size_t)a * 3 + 2];
    float bx = r[(size_t)b * 3 + 0], by = r[(size_t)b * 3 + 1], bz = r[(size_t)b * 3 + 2];
    float dot = -(ax * bx + ay * by + az * bz);
    float na = sqrtf(ax * ax + ay * ay + az * az);
    float nb = sqrtf(bx * bx + by * by + bz * bz);
    float c = dot / (na * nb);
    out[t] = fminf(1.f, fmaxf(-1.f, c));
}

__global__ void bondlen_kernel(const float* __restrict__ r, float* __restrict__ out, int Ecnt) {
    int e = blockIdx.x * blockDim.x + threadIdx.x;
    if (e >= Ecnt) return;
    float x = r[(size_t)e * 3 + 0], y = r[(size_t)e * 3 + 1], z = r[(size_t)e * 3 + 2];
    out[e] = sqrtf(x * x + y * y + z * z);
}

__global__ void rbf_kernel(const float* __restrict__ vals, float* __restrict__ out,
                           long long M, int bins, float vmin, float vmax) {
    long long idx = (long long)blockIdx.x * blockDim.x + threadIdx.x;
    long long total = M * bins;
    if (idx >= total) return;
    long long t = idx / bins;
    int k = (int)(idx % bins);
    float spacing = (vmax - vmin) / (bins - 1);
    float center = vmin + k * spacing;
    float gamma = 1.f / spacing;
    float d = vals[t] - center;
    out[idx] = __expf(-gamma * d * d);
}

// ---------------- output head ----------------
__global__ void fc_kernel(const float* __restrict__ x, const float* __restrict__ W,
                          const float* __restrict__ b, float* __restrict__ out) {
    int atom = blockIdx.x * 8 + (threadIdx.x >> 5);
    if (atom >= NN) return;
    int lane = threadIdx.x & 31;
    float sum = 0.f;
    #pragma unroll
    for (int i = 0; i < 8; i++) {
        int c = lane + i * 32;
        sum += x[(size_t)atom * HH + c] * W[c];
    }
    #pragma unroll
    for (int o = 16; o; o >>= 1) sum += __shfl_xor_sync(0xffffffffu, sum, o);
    if (lane == 0) out[1 + atom] = sum + b[0];
}

__global__ void mean_kernel(float* out) {
    __shared__ float sh[32];
    float s = 0.f;
    for (int i = threadIdx.x; i < NN; i += 1024) s += out[1 + i];
    #pragma unroll
    for (int o = 16; o; o >>= 1) s += __shfl_xor_sync(0xffffffffu, s, o);
    if ((threadIdx.x & 31) == 0) sh[threadIdx.x >> 5] = s;
    __syncthreads();
    if (threadIdx.x < 32) {
        s = sh[threadIdx.x];
        #pragma unroll
        for (int o = 16; o; o >>= 1) s += __shfl_xor_sync(0xffffffffu, s, o);
        if (threadIdx.x == 0) out[0] = s / (float)NN;
    }
}

extern "C" void kernel_launch(void* const* d_in, const int* in_sizes, int n_in,
                              void* d_out, int out_size) {
    const float* atom_features = (const float*)d_in[0];
    const float* r    = (const float*)d_in[1];
    const int*   src  = (const int*)d_in[2];
    const int*   dst  = (const int*)d_in[3];
    const int*   lsrc = (const int*)d_in[4];
    const int*   ldst = (const int*)d_in[5];
    const float* atom_W    = (const float*)d_in[6];
    const float* atom_b    = (const float*)d_in[7];
    const float* atom_ln_s = (const float*)d_in[8];
    const float* atom_ln_b = (const float*)d_in[9];
    const float* edge_W1    = (const float*)d_in[10];
    const float* edge_b1    = (const float*)d_in[11];
    const float* edge_ln1_s = (const float*)d_in[12];
    const float* edge_ln1_b = (const float*)d_in[13];
    const float* edge_W2    = (const float*)d_in[14];
    const float* edge_b2    = (const float*)d_in[15];
    const float* edge_ln2_s = (const float*)d_in[16];
    const float* edge_ln2_b = (const float*)d_in[17];
    const float* ang_W1    = (const float*)d_in[18];
    const float* ang_b1    = (const float*)d_in[19];
    const float* ang_ln1_s = (const float*)d_in[20];
    const float* ang_ln1_b = (const float*)d_in[21];
    const float* ang_W2    = (const float*)d_in[22];
    const float* ang_b2    = (const float*)d_in[23];
    const float* ang_ln2_s = (const float*)d_in[24];
    const float* ang_ln2_b = (const float*)d_in[25];
    const float* eggc_W    = (const float*)d_in[26];
    const float* eggc_b    = (const float*)d_in[27];
    const float* eggc_ln_s = (const float*)d_in[28];
    const float* eggc_ln_b = (const float*)d_in[29];
    const float* fc_W = (const float*)d_in[30];
    const float* fc_b = (const float*)d_in[31];
    float* out = (float*)d_out;

    float *px, *psums, *psumsh, *prbf, *pval;
    __half *hg0, *hg1, *hg3, *hg4, *hm;
    __half *hx, *hy, *hz, *hh, *wh;
    cudaGetSymbolAddress((void**)&px,    g_x);
    cudaGetSymbolAddress((void**)&psums, g_sums);
    cudaGetSymbolAddress((void**)&psumsh,g_sumsh);
    cudaGetSymbolAddress((void**)&prbf,  g_rbf);
    cudaGetSymbolAddress((void**)&pval,  g_val);
    cudaGetSymbolAddress((void**)&hg0,   g_hg0);
    cudaGetSymbolAddress((void**)&hg1,   g_hg1);
    cudaGetSymbolAddress((void**)&hg3,   g_hg3);
    cudaGetSymbolAddress((void**)&hg4,   g_hg4);
    cudaGetSymbolAddress((void**)&hm,    g_hm);
    cudaGetSymbolAddress((void**)&hx,    g_hx);
    cudaGetSymbolAddress((void**)&hy,    g_hy);
    cudaGetSymbolAddress((void**)&hz,    g_hz);
    cudaGetSymbolAddress((void**)&hh,    g_hh);
    cudaGetSymbolAddress((void**)&wh,    g_wh);

    cudaFuncSetAttribute(f16_gemm256_kernel<0>, cudaFuncAttributeMaxDynamicSharedMemorySize, F16SMEM);
    cudaFuncSetAttribute(f16_gemm256_kernel<1>, cudaFuncAttributeMaxDynamicSharedMemorySize, F16SMEM);
    cudaFuncSetAttribute(f16_gemm256_kernel<2>, cudaFuncAttributeMaxDynamicSharedMemorySize, F16SMEM);

    // ---- convert + transpose weights to fp16 [N,K] ----
    {
        dim3 tb(32, 8);
        wconv_kernel<<<dim3(8, 8, 60), tb>>>(eggc_W, wh, 256, 256);
        wconv_kernel<<<dim3(2, 8, 1), tb>>>(ang_W2, wh + WT_ANG, 64, 256);
        wconv_kernel<<<dim3(2, 8, 1), tb>>>(edge_W2, wh + WT_EDGE, 64, 256);
    }

    // ---- angle branch: z = fp16-only state ----
    cos_kernel<<<TT / 256, 256>>>(r, lsrc, ldst, pval, TT);
    {
        long long total = (long long)TT * TB;
        rbf_kernel<<<(unsigned)((total + 255) / 256), 256>>>(pval, prbf, TT, TB, -1.f, 1.f);
    }
    {
        dim3 grid(1, TT / 64);
        sgemm_bias_kernel<<<grid, 256>>>(prbf, ang_W1, ang_b1, nullptr, hh,
                                         TT, EMB, TB, ang_ln1_s, ang_ln1_b, 1);
    }
    {
        dim3 grid(TT / 128, 1);
        f16_gemm256_kernel<2><<<grid, 256, F16SMEM>>>(
            hh, wh + WT_ANG, wh + WT_ANG, wh + WT_ANG, wh + WT_ANG,
            ang_b2, ang_b2, ang_b2, ang_b2,
            nullptr, nullptr, nullptr, nullptr,
            nullptr, hz, ang_ln2_s, ang_ln2_b, nullptr, nullptr, TT, EMB);
    }

    // ---- edge branch: y = fp16-only state ----
    bondlen_kernel<<<EE / 256, 256>>>(r, pval, EE);
    {
        long long total = (long long)EE * EB;
        rbf_kernel<<<(unsigned)((total + 255) / 256), 256>>>(pval, prbf, EE, EB, 0.f, 8.f);
    }
    {
        dim3 grid(1, EE / 64);
        sgemm_bias_kernel<<<grid, 256>>>(prbf, edge_W1, edge_b1, nullptr, hh,
                                         EE, EMB, EB, edge_ln1_s, edge_ln1_b, 1);
    }
    {
        dim3 grid(EE / 128, 1);
        f16_gemm256_kernel<2><<<grid, 256, F16SMEM>>>(
            hh, wh + WT_EDGE, wh + WT_EDGE, wh + WT_EDGE, wh + WT_EDGE,
            edge_b2, edge_b2, edge_b2, edge_b2,
            nullptr, nullptr, nullptr, nullptr,
            nullptr, hy, edge_ln2_s, edge_ln2_b, nullptr, nullptr, EE, EMB);
    }

    // ---- atom branch (x stays fp32 + mirror: feeds output head) ----
    {
        dim3 grid(HH / 64, NN / 64);
        sgemm_bias_kernel<<<grid, 256>>>(atom_features, atom_W, atom_b, px, nullptr,
                                         NN, HH, AIN, nullptr, nullptr, 0);
    }
    ln_silu_kernel<<<NN / 8, 256>>>(px, atom_ln_s, atom_ln_b, px, hx, NN, HH);

    // ---- 12 EGGC blocks ----
    for (int blk = 0; blk < 12; blk++) {
        bool line = (blk < 8) && (blk & 1);
        __half* nodeh = line ? hy : hx;
        int n        = line ? EE : NN;
        __half* edgeh = line ? hz : hy;
        int e        = line ? TT : EE;
        const int* gs = line ? lsrc : src;
        const int* gd = line ? ldst : dst;
        const float* bb = eggc_b   + (size_t)blk * 5 * HH;
        const float* ls = eggc_ln_s + (size_t)blk * 2 * HH;
        const float* lb = eggc_ln_b + (size_t)blk * 2 * HH;

        // 4 node-side GEMMs in one launch (shared A); also zeros psums (y=0) and psumsh (y=1)
        {
            dim3 grid(n / 128, 4);
            f16_gemm256_kernel<0><<<grid, 256, F16SMEM>>>(
                nodeh,
                wh + WT_EGGC(blk, 0), wh + WT_EGGC(blk, 1), wh + WT_EGGC(blk, 3), wh + WT_EGGC(blk, 4),
                bb + 0 * HH, bb + 1 * HH, bb + 3 * HH, bb + 4 * HH,
                hg0, hg1, hg3, hg4,
                nullptr, nullptr, nullptr, nullptr,
                psums, psumsh, n, HH);
        }
        // edge gate GEMM -> hm (fp16)
        {
            dim3 grid(e / 128, 1);
            f16_gemm256_kernel<0><<<grid, 256, F16SMEM>>>(
                edgeh,
                wh + WT_EGGC(blk, 2), wh + WT_EGGC(blk, 2), wh + WT_EGGC(blk, 2), wh + WT_EGGC(blk, 2),
                bb + 2 * HH, bb + 2 * HH, bb + 2 * HH, bb + 2 * HH,
                hm, hm, hm, hm,
                nullptr, nullptr, nullptr, nullptr,
                nullptr, nullptr, e, HH);
        }

        eggc_msg_ln_kernel<<<e / 8, 256>>>((const uint4*)hg0, (const uint4*)hg1,
                                           (const uint4*)hg4, (const uint4*)hm,
                                           gs, gd, psums, psumsh,
                                           (const float4*)(ls + HH), (const float4*)(lb + HH),
                                           edgeh, e);

        if (line) {
            node_update_kernel<1><<<(n + 7) / 8, 256>>>(hg3, psumsh, psums, ls, lb,
                                                        nullptr, hy, n);
        } else {
            node_update_kernel<0><<<(n + 7) / 8, 256>>>(hg3, psumsh, psums, ls, lb,
                                                        px, hx, n);
        }
    }

    // ---- output head ----
    fc_kernel<<<(NN + 7) / 8, 256>>>(px, fc_W, fc_b, out);
    mean_kernel<<<1, 1024>>>(out);
}